// round 9
// baseline (speedup 1.0000x reference)
#include <cuda_runtime.h>
#include <cuda_bf16.h>
#include <stdint.h>

#define T_TOK 1024
#define D_DIM 1024
#define F_DIM 2048
#define E_EXP 32
#define TOPK  4
#define NPAIR (T_TOK * TOPK)
#define MAXW  72

// ---------------- static scratch ----------------
__device__ int      g_cnt[E_EXP];
__device__ int      g_pairs[E_EXP * T_TOK];
__device__ float    g_w[NPAIR];
__device__ uint32_t g_hp[(size_t)NPAIR * F_DIM];   // routed hidden packed bf16 hi|lo<<16
__device__ uint32_t g_hsp[(size_t)T_TOK * F_DIM];  // shared hidden packed
__device__ float    g_y[(size_t)NPAIR * D_DIM];    // routed per-pair down output
__device__ int      g_nwork;
__device__ int      g_work[MAXW];                  // (z<<16)|mt ; z==E_EXP -> shared

// ---------------- helpers ----------------
__device__ __forceinline__ uint32_t smem_u32(const void* p) {
    uint32_t a;
    asm("{ .reg .u64 t; cvta.to.shared.u64 t, %1; cvt.u32.u64 %0, t; }" : "=r"(a) : "l"(p));
    return a;
}
__device__ __forceinline__ void ldm4(uint32_t* r, uint32_t addr) {
    asm volatile("ldmatrix.sync.aligned.m8n8.x4.shared.b16 {%0,%1,%2,%3}, [%4];"
                 : "=r"(r[0]), "=r"(r[1]), "=r"(r[2]), "=r"(r[3]) : "r"(addr));
}
__device__ __forceinline__ void mma16816(float* d, const uint32_t* a, const uint32_t* b) {
    asm volatile("mma.sync.aligned.m16n8k16.row.col.f32.bf16.bf16.f32 "
                 "{%0,%1,%2,%3}, {%4,%5,%6,%7}, {%8,%9}, {%0,%1,%2,%3};"
                 : "+f"(d[0]), "+f"(d[1]), "+f"(d[2]), "+f"(d[3])
                 : "r"(a[0]), "r"(a[1]), "r"(a[2]), "r"(a[3]), "r"(b[0]), "r"(b[1]));
}
__device__ __forceinline__ void cvt_split(float x0, float x1, uint32_t& hi, uint32_t& lo) {
    asm("cvt.rn.bf16x2.f32 %0, %1, %2;" : "=r"(hi) : "f"(x1), "f"(x0));
    float f0 = __uint_as_float(hi << 16);
    float f1 = __uint_as_float(hi & 0xffff0000u);
    float r0 = x0 - f0, r1 = x1 - f1;
    asm("cvt.rn.bf16x2.f32 %0, %1, %2;" : "=r"(lo) : "f"(r1), "f"(r0));
}
__device__ __forceinline__ void split_store4(char* hi, char* lo, float4 v) {
    uint32_t h0, l0, h1, l1;
    cvt_split(v.x, v.y, h0, l0);
    cvt_split(v.z, v.w, h1, l1);
    *(uint2*)hi = make_uint2(h0, h1);
    *(uint2*)lo = make_uint2(l0, l1);
}
__device__ __forceinline__ uint32_t pack_split1(float h) {
    __nv_bfloat16 hb = __float2bfloat16_rn(h);
    float r = h - __bfloat162float(hb);
    __nv_bfloat16 lb = __float2bfloat16_rn(r);
    return (uint32_t)__bfloat16_as_ushort(hb) | ((uint32_t)__bfloat16_as_ushort(lb) << 16);
}

// ---------------- tiny kernels ----------------
__global__ void zero_kernel() {
    if (threadIdx.x < E_EXP) g_cnt[threadIdx.x] = 0;
}

__global__ void router_kernel(const float* __restrict__ x,
                              const float* __restrict__ gw,
                              const float* __restrict__ bias) {
    __shared__ float xs[D_DIM];
    __shared__ float logits[E_EXP];
    int t = blockIdx.x;
    const float4* xr = (const float4*)(x + (size_t)t * D_DIM);
    for (int i = threadIdx.x; i < D_DIM / 4; i += blockDim.x)
        ((float4*)xs)[i] = xr[i];
    __syncthreads();

    int e = threadIdx.x >> 2;
    int g = threadIdx.x & 3;
    const float4* wrow = (const float4*)(gw + (size_t)e * D_DIM);
    float s = 0.f;
    for (int d4 = g; d4 < D_DIM / 4; d4 += 4) {
        float4 a = ((const float4*)xs)[d4];
        float4 b = wrow[d4];
        s += a.x * b.x + a.y * b.y + a.z * b.z + a.w * b.w;
    }
    s += __shfl_down_sync(0xffffffffu, s, 2, 4);
    s += __shfl_down_sync(0xffffffffu, s, 1, 4);
    if (g == 0) logits[e] = s + bias[e];
    __syncthreads();

    if (threadIdx.x == 0) {
        float v[TOPK]; int idx[TOPK];
        unsigned used = 0;
        for (int k = 0; k < TOPK; k++) {
            float best = -3.4e38f; int bi = 0;
            for (int j = 0; j < E_EXP; j++) {
                if (used & (1u << j)) continue;
                if (logits[j] > best) { best = logits[j]; bi = j; }
            }
            used |= 1u << bi; v[k] = best; idx[k] = bi;
        }
        float ex[TOPK], sum = 0.f;
        for (int k = 0; k < TOPK; k++) { ex[k] = __expf(v[k] - v[0]); sum += ex[k]; }
        float inv = 1.f / sum;
        for (int k = 0; k < TOPK; k++) {
            int ek = idx[k];
            int slot = atomicAdd(&g_cnt[ek], 1);
            g_pairs[ek * T_TOK + slot] = t * TOPK + k;
            g_w[t * TOPK + k] = ex[k] * inv;
        }
    }
}

// stats + compact work-list builder (128-row tiles)
__global__ void stats_kernel(float* __restrict__ tail) {
    int e = threadIdx.x;
    float c = (float)g_cnt[e];
    float mean = (float)(T_TOK * TOPK) / E_EXP;
    float d = c - mean;
    float v = d * d;
    for (int o = 16; o > 0; o >>= 1) v += __shfl_down_sync(0xffffffffu, v, o);
    if (tail) {
        tail[e] = c;
        if (e == 0) tail[E_EXP] = sqrtf(v / E_EXP) / (mean + 1e-6f);
    }
    if (threadIdx.x == 0) {
        int n = 0;
        for (int z = 0; z < E_EXP; ++z) {
            int tiles = (g_cnt[z] + 127) >> 7;
            for (int mt = 0; mt < tiles && n < MAXW; ++mt)
                g_work[n++] = (z << 16) | mt;
        }
        for (int mt = 0; mt < T_TOK / 128 && n < MAXW; ++mt)
            g_work[n++] = (E_EXP << 16) | mt;
        g_nwork = n;
    }
}

// ================= gate+up warp-specialized =================
// CTA 128M x 64N(F), 512 thr: warps 0-7 consumers (4 gate + 4 up, 32x64 tiles),
// warps 8-15 producers (LDG + split + STS). BK=64, double buffered.
#define APITCH 144
#define GU_A_HI 0
#define GU_A_LO 18432
#define GU_BG_HI 36864
#define GU_BG_LO 46080
#define GU_BU_HI 55296
#define GU_BU_LO 64512
#define GU_STAGE 73728
#define GU_SMEM (1024 + 2 * GU_STAGE)   // 148480

__global__ void __launch_bounds__(512, 1)
gu_mma(const float* __restrict__ x,
       const float* __restrict__ Wg, const float* __restrict__ Wu,
       const float* __restrict__ wsg, const float* __restrict__ wsu) {
    extern __shared__ char smem[];
    int tid = threadIdx.x;
    int wi = blockIdx.y;
    if (wi >= g_nwork) return;
    int code = g_work[wi];
    int z = code >> 16;
    int mtile = code & 0xffff;
    bool SH = (z == E_EXP);
    int ne = SH ? T_TOK : g_cnt[z];
    int m0 = mtile * 128;
    int n0 = blockIdx.x * 64;
    const float* wgp = SH ? wsg : (Wg + (size_t)z * F_DIM * D_DIM);
    const float* wup = SH ? wsu : (Wu + (size_t)z * F_DIM * D_DIM);

    int* s_pair = (int*)smem;
    int* s_src  = (int*)(smem + 512);
    if (tid < 128) {
        int m = m0 + tid;
        int pair = SH ? m : ((m < ne) ? g_pairs[z * T_TOK + m] : g_pairs[z * T_TOK]);
        s_pair[tid] = pair;
        s_src[tid]  = SH ? m : (pair >> 2);
    }
    __syncthreads();

    const int wid = tid >> 5, lane = tid & 31;
    const bool isProd = wid >= 8;

    // producer state
    const float* aptr[8];
    const float* gptr[4];
    const float* uptr[4];
    unsigned soA[8], soB[4];
    if (isProd) {
        int ptid = tid - 256;
#pragma unroll
        for (int j = 0; j < 8; ++j) {
            int idx = ptid + 256 * j;
            int row = idx >> 4, c4 = idx & 15;
            aptr[j] = x + (size_t)s_src[row] * D_DIM + c4 * 4;
            soA[j]  = row * APITCH + c4 * 8;
        }
#pragma unroll
        for (int j = 0; j < 4; ++j) {
            int idx = ptid + 256 * j;
            int row = idx >> 4, c4 = idx & 15;
            gptr[j] = wgp + (size_t)(n0 + row) * D_DIM + c4 * 4;
            uptr[j] = wup + (size_t)(n0 + row) * D_DIM + c4 * 4;
            soB[j]  = row * APITCH + c4 * 8;
        }
    }

    // consumer state: 32x64 tile; gate warps 0-3 (rows q*32), up warps 4-7
    const bool isUp = (wid & 4) != 0;
    const int q = wid & 3;
    const uint32_t a_row  = q * 32 + (lane & 15);
    const uint32_t a_cb   = (lane >> 4) * 16;
    const uint32_t b_row  = ((lane >> 3) >> 1) * 8 + (lane & 7);
    const uint32_t b_cb   = ((lane >> 3) & 1) * 16;

    float acc[2][8][4] = {};

#define GU_FILL(BUF, K0) do { char* b_ = (BUF); int k_ = (K0); \
    _Pragma("unroll") \
    for (int j = 0; j < 8; ++j) { \
        float4 v = *(const float4*)(aptr[j] + k_); \
        split_store4(b_ + GU_A_HI + soA[j], b_ + GU_A_LO + soA[j], v); } \
    _Pragma("unroll") \
    for (int j = 0; j < 4; ++j) { \
        float4 vg = *(const float4*)(gptr[j] + k_); \
        split_store4(b_ + GU_BG_HI + soB[j], b_ + GU_BG_LO + soB[j], vg); \
        float4 vu = *(const float4*)(uptr[j] + k_); \
        split_store4(b_ + GU_BU_HI + soB[j], b_ + GU_BU_LO + soB[j], vu); } } while (0)

    if (isProd) GU_FILL(smem + 1024, 0);
    __syncthreads();

    for (int ch = 0; ch < 16; ++ch) {
        if (isProd) {
            if (ch < 15) GU_FILL(smem + 1024 + ((ch + 1) & 1) * GU_STAGE, (ch + 1) * 64);
        } else {
            uint32_t ab = smem_u32(smem + 1024 + (ch & 1) * GU_STAGE);
            uint32_t bb = ab + (isUp ? GU_BU_HI : GU_BG_HI);
#pragma unroll
            for (int ks = 0; ks < 4; ++ks) {
                uint32_t koff = ks * 32;
                uint32_t ah[2][4], al[2][4];
#pragma unroll
                for (int mt2 = 0; mt2 < 2; ++mt2) {
                    uint32_t ad = ab + GU_A_HI + (a_row + mt2 * 16) * APITCH + koff + a_cb;
                    ldm4(ah[mt2], ad);
                    ldm4(al[mt2], ad + (GU_A_LO - GU_A_HI));
                }
#pragma unroll
                for (int h = 0; h < 2; ++h) {
                    uint32_t bh[8], bl[8];
#pragma unroll
                    for (int p2 = 0; p2 < 2; ++p2) {
                        uint32_t bd = bb + (b_row + (h * 2 + p2) * 16) * APITCH + koff + b_cb;
                        ldm4(&bh[p2 * 4], bd);
                        ldm4(&bl[p2 * 4], bd + (GU_BG_LO - GU_BG_HI));
                    }
#pragma unroll
                    for (int mt2 = 0; mt2 < 2; ++mt2)
#pragma unroll
                        for (int nt = 0; nt < 4; ++nt) {
                            float* d = acc[mt2][h * 4 + nt];
                            mma16816(d, ah[mt2], &bh[nt * 2]);
                            mma16816(d, ah[mt2], &bl[nt * 2]);
                            mma16816(d, al[mt2], &bh[nt * 2]);
                        }
                }
            }
        }
        __syncthreads();
    }

    // epilogue: consumers stage fp32 gate/up (pitch 68), all threads pack+store
    float* stg_g = (float*)(smem + 1024);
    float* stg_u = stg_g + 128 * 68;
    if (!isProd) {
        float* my = isUp ? stg_u : stg_g;
#pragma unroll
        for (int mt2 = 0; mt2 < 2; ++mt2)
#pragma unroll
            for (int nt = 0; nt < 8; ++nt) {
                int r = q * 32 + mt2 * 16 + (lane >> 2);
                int c = nt * 8 + (lane & 3) * 2;
                *(float2*)&stg_g[0] ;  // no-op anchor (kept simple below)
                *(float2*)&my[r * 68 + c]       = make_float2(acc[mt2][nt][0], acc[mt2][nt][1]);
                *(float2*)&my[(r + 8) * 68 + c] = make_float2(acc[mt2][nt][2], acc[mt2][nt][3]);
            }
    }
    __syncthreads();

    uint32_t* dst = SH ? g_hsp : g_hp;
    {
        int r = tid >> 2;
        int c0 = (tid & 3) * 16;
        uint32_t* drow = dst + (size_t)s_pair[r] * F_DIM + n0 + c0;
#pragma unroll
        for (int jj = 0; jj < 16; jj += 4) {
            uint4 o;
            uint32_t* po = &o.x;
#pragma unroll
            for (int k = 0; k < 4; ++k) {
                float gg = stg_g[r * 68 + c0 + jj + k];
                float uu = stg_u[r * 68 + c0 + jj + k];
                float h = gg / (1.f + __expf(-gg)) * uu;
                po[k] = pack_split1(h);
            }
            *(uint4*)(drow + jj) = o;
        }
    }
}

// ================= down warp-specialized =================
// CTA 128M x 64N(D), 256 thr: warps 0-3 consumers (32x64), warps 4-7 producers.
// BK=64 over F, double buffered, 2 CTAs/SM.
#define DN_A_HI 0
#define DN_A_LO 18432
#define DN_B_HI 36864
#define DN_B_LO 46080
#define DN_STAGE 55296
#define DN_SMEM (1024 + 2 * DN_STAGE)   // 111616

__global__ void __launch_bounds__(256, 2)
dn_mma(const float* __restrict__ Wd, const float* __restrict__ wsd,
       float* __restrict__ out) {
    extern __shared__ char smem[];
    int tid = threadIdx.x;
    int wi = blockIdx.y;
    if (wi >= g_nwork) return;
    int code = g_work[wi];
    int z = code >> 16;
    int mtile = code & 0xffff;
    bool SH = (z == E_EXP);
    int ne = SH ? T_TOK : g_cnt[z];
    int m0 = mtile * 128;
    int n0 = blockIdx.x * 64;
    const float* wdp = SH ? wsd : (Wd + (size_t)z * D_DIM * F_DIM);
    const uint32_t* hsrc = SH ? g_hsp : g_hp;

    int* s_pair = (int*)smem;
    if (tid < 128) {
        int m = m0 + tid;
        s_pair[tid] = SH ? m : ((m < ne) ? g_pairs[z * T_TOK + m] : g_pairs[z * T_TOK]);
    }
    __syncthreads();

    const int wid = tid >> 5, lane = tid & 31;
    const bool isProd = wid >= 4;

    const uint32_t* aptr[16];
    const float*    bptr[8];
    unsigned soA[16], soB[8];
    if (isProd) {
        int ptid = tid - 128;
#pragma unroll
        for (int j = 0; j < 16; ++j) {
            int idx = ptid + 128 * j;
            int row = idx >> 4, c4 = idx & 15;
            aptr[j] = hsrc + (size_t)(SH ? (m0 + row) : s_pair[row]) * F_DIM + c4 * 4;
            soA[j]  = row * APITCH + c4 * 8;
        }
#pragma unroll
        for (int j = 0; j < 8; ++j) {
            int idx = ptid + 128 * j;
            int row = idx >> 4, c4 = idx & 15;
            bptr[j] = wdp + (size_t)(n0 + row) * F_DIM + c4 * 4;
            soB[j]  = row * APITCH + c4 * 8;
        }
    }

    const uint32_t a_row = wid * 32 + (lane & 15);   // consumers: wid 0..3
    const uint32_t a_cb  = (lane >> 4) * 16;
    const uint32_t b_row = ((lane >> 3) >> 1) * 8 + (lane & 7);
    const uint32_t b_cb  = ((lane >> 3) & 1) * 16;

    float acc[2][8][4] = {};

#define DN_FILL(BUF, K0) do { char* b_ = (BUF); int k_ = (K0); \
    _Pragma("unroll") \
    for (int j = 0; j < 16; ++j) { \
        uint4 pv = *(const uint4*)(aptr[j] + k_); \
        uint32_t h0 = __byte_perm(pv.x, pv.y, 0x5410); \
        uint32_t h1 = __byte_perm(pv.z, pv.w, 0x5410); \
        uint32_t l0 = __byte_perm(pv.x, pv.y, 0x7632); \
        uint32_t l1 = __byte_perm(pv.z, pv.w, 0x7632); \
        *(uint2*)(b_ + DN_A_HI + soA[j]) = make_uint2(h0, h1); \
        *(uint2*)(b_ + DN_A_LO + soA[j]) = make_uint2(l0, l1); } \
    _Pragma("unroll") \
    for (int j = 0; j < 8; ++j) { \
        float4 v = *(const float4*)(bptr[j] + k_); \
        split_store4(b_ + DN_B_HI + soB[j], b_ + DN_B_LO + soB[j], v); } } while (0)

    if (isProd) DN_FILL(smem + 1024, 0);
    __syncthreads();

    for (int ch = 0; ch < 32; ++ch) {
        if (isProd) {
            if (ch < 31) DN_FILL(smem + 1024 + ((ch + 1) & 1) * DN_STAGE, (ch + 1) * 64);
        } else {
            uint32_t ab = smem_u32(smem + 1024 + (ch & 1) * DN_STAGE);
#pragma unroll
            for (int ks = 0; ks < 4; ++ks) {
                uint32_t koff = ks * 32;
                uint32_t ah[2][4], al[2][4];
#pragma unroll
                for (int mt2 = 0; mt2 < 2; ++mt2) {
                    uint32_t ad = ab + DN_A_HI + (a_row + mt2 * 16) * APITCH + koff + a_cb;
                    ldm4(ah[mt2], ad);
                    ldm4(al[mt2], ad + (DN_A_LO - DN_A_HI));
                }
#pragma unroll
                for (int h = 0; h < 2; ++h) {
                    uint32_t bh[8], bl[8];
#pragma unroll
                    for (int p2 = 0; p2 < 2; ++p2) {
                        uint32_t bd = ab + DN_B_HI + (b_row + (h * 2 + p2) * 16) * APITCH + koff + b_cb;
                        ldm4(&bh[p2 * 4], bd);
                        ldm4(&bl[p2 * 4], bd + (DN_B_LO - DN_B_HI));
                    }
#pragma unroll
                    for (int mt2 = 0; mt2 < 2; ++mt2)
#pragma unroll
                        for (int nt = 0; nt < 4; ++nt) {
                            float* d = acc[mt2][h * 4 + nt];
                            mma16816(d, ah[mt2], &bh[nt * 2]);
                            mma16816(d, ah[mt2], &bl[nt * 2]);
                            mma16816(d, al[mt2], &bh[nt * 2]);
                        }
                }
            }
        }
        __syncthreads();
    }

    // epilogue: consumers stage 128x64 fp32 (pitch 68), all threads store
    float* stg = (float*)(smem + 1024);
    if (!isProd) {
#pragma unroll
        for (int mt2 = 0; mt2 < 2; ++mt2)
#pragma unroll
            for (int nt = 0; nt < 8; ++nt) {
                int r = wid * 32 + mt2 * 16 + (lane >> 2);
                int c = nt * 8 + (lane & 3) * 2;
                *(float2*)&stg[r * 68 + c]       = make_float2(acc[mt2][nt][0], acc[mt2][nt][1]);
                *(float2*)&stg[(r + 8) * 68 + c] = make_float2(acc[mt2][nt][2], acc[mt2][nt][3]);
            }
    }
    __syncthreads();

    {
        int r = tid >> 1, c0 = (tid & 1) * 32;
        float* drow;
        if (SH) drow = out + (size_t)(m0 + r) * D_DIM + n0 + c0;
        else    drow = g_y + (size_t)s_pair[r] * D_DIM + n0 + c0;
#pragma unroll
        for (int jj = 0; jj < 32; jj += 4)
            *(float4*)(drow + jj) = make_float4(stg[r * 68 + c0 + jj],     stg[r * 68 + c0 + jj + 1],
                                                stg[r * 68 + c0 + jj + 2], stg[r * 68 + c0 + jj + 3]);
    }
}

// ================= combine: out += sum_k w_k * y_pair =================
__global__ void combine_kernel(float* __restrict__ out) {
    int t = blockIdx.x;
    int c = threadIdx.x * 4;
    float4 o = *(float4*)(out + (size_t)t * D_DIM + c);
#pragma unroll
    for (int k = 0; k < TOPK; ++k) {
        int pair = t * TOPK + k;
        float w = g_w[pair];
        float4 y = *(const float4*)(g_y + (size_t)pair * D_DIM + c);
        o.x += w * y.x; o.y += w * y.y; o.z += w * y.z; o.w += w * y.w;
    }
    *(float4*)(out + (size_t)t * D_DIM + c) = o;
}

// ---------------- launch ----------------
extern "C" void kernel_launch(void* const* d_in, const int* in_sizes, int n_in,
                              void* d_out, int out_size) {
    const float* x    = (const float*)d_in[0];
    const float* gw   = (const float*)d_in[1];
    const float* bias = (const float*)d_in[2];
    const float* wg   = (const float*)d_in[3];
    const float* wu   = (const float*)d_in[4];
    const float* wd   = (const float*)d_in[5];
    const float* wsg  = (const float*)d_in[6];
    const float* wsu  = (const float*)d_in[7];
    const float* wsd  = (const float*)d_in[8];
    float* out = (float*)d_out;

    static int attr_done = 0;
    if (!attr_done) {
        cudaFuncSetAttribute(gu_mma, cudaFuncAttributeMaxDynamicSharedMemorySize, GU_SMEM);
        cudaFuncSetAttribute(dn_mma, cudaFuncAttributeMaxDynamicSharedMemorySize, DN_SMEM);
        attr_done = 1;
    }

    zero_kernel<<<1, 32>>>();
    router_kernel<<<T_TOK, 128>>>(x, gw, bias);

    float* tail = (out_size >= T_TOK * D_DIM + E_EXP + 1) ? (out + T_TOK * D_DIM) : nullptr;
    stats_kernel<<<1, 32>>>(tail);

    // gate+up: work-list scheduled, warp-specialized
    gu_mma<<<dim3(F_DIM / 64, MAXW), 512, GU_SMEM>>>(x, wg, wu, wsg, wsu);

    // down: work-list scheduled, warp-specialized, 2 CTAs/SM
    dn_mma<<<dim3(D_DIM / 64, MAXW), 256, DN_SMEM>>>(wd, wsd, out);

    // weighted combine
    combine_kernel<<<T_TOK, 256>>>(out);
}

// round 10
// speedup vs baseline: 1.5638x; 1.5638x over previous
#include <cuda_runtime.h>
#include <cuda_bf16.h>
#include <stdint.h>

#define T_TOK 1024
#define D_DIM 1024
#define F_DIM 2048
#define E_EXP 32
#define TOPK  4
#define NPAIR (T_TOK * TOPK)
#define MAXW  96

// ---------------- static scratch ----------------
__device__ int      g_cnt[E_EXP];
__device__ int      g_pairs[E_EXP * T_TOK];
__device__ float    g_w[NPAIR];
__device__ uint32_t g_hp[(size_t)NPAIR * F_DIM];   // routed hidden packed bf16 hi|lo<<16
__device__ uint32_t g_hsp[(size_t)T_TOK * F_DIM];  // shared hidden packed
__device__ float    g_y[(size_t)NPAIR * D_DIM];    // routed per-pair down output
__device__ int      g_nwork;
__device__ int      g_work[MAXW];                  // (z<<16)|mt ; z==E_EXP -> shared

// ---------------- helpers ----------------
__device__ __forceinline__ uint32_t smem_u32(const void* p) {
    uint32_t a;
    asm("{ .reg .u64 t; cvta.to.shared.u64 t, %1; cvt.u32.u64 %0, t; }" : "=r"(a) : "l"(p));
    return a;
}
__device__ __forceinline__ void ldm4(uint32_t* r, uint32_t addr) {
    asm volatile("ldmatrix.sync.aligned.m8n8.x4.shared.b16 {%0,%1,%2,%3}, [%4];"
                 : "=r"(r[0]), "=r"(r[1]), "=r"(r[2]), "=r"(r[3]) : "r"(addr));
}
__device__ __forceinline__ void mma16816(float* d, const uint32_t* a, const uint32_t* b) {
    asm volatile("mma.sync.aligned.m16n8k16.row.col.f32.bf16.bf16.f32 "
                 "{%0,%1,%2,%3}, {%4,%5,%6,%7}, {%8,%9}, {%0,%1,%2,%3};"
                 : "+f"(d[0]), "+f"(d[1]), "+f"(d[2]), "+f"(d[3])
                 : "r"(a[0]), "r"(a[1]), "r"(a[2]), "r"(a[3]), "r"(b[0]), "r"(b[1]));
}
__device__ __forceinline__ void cvt_split(float x0, float x1, uint32_t& hi, uint32_t& lo) {
    asm("cvt.rn.bf16x2.f32 %0, %1, %2;" : "=r"(hi) : "f"(x1), "f"(x0));
    float f0 = __uint_as_float(hi << 16);
    float f1 = __uint_as_float(hi & 0xffff0000u);
    float r0 = x0 - f0, r1 = x1 - f1;
    asm("cvt.rn.bf16x2.f32 %0, %1, %2;" : "=r"(lo) : "f"(r1), "f"(r0));
}
__device__ __forceinline__ void split_store4(char* hi, char* lo, float4 v) {
    uint32_t h0, l0, h1, l1;
    cvt_split(v.x, v.y, h0, l0);
    cvt_split(v.z, v.w, h1, l1);
    *(uint2*)hi = make_uint2(h0, h1);
    *(uint2*)lo = make_uint2(l0, l1);
}
__device__ __forceinline__ uint32_t pack_split1(float h) {
    __nv_bfloat16 hb = __float2bfloat16_rn(h);
    float r = h - __bfloat162float(hb);
    __nv_bfloat16 lb = __float2bfloat16_rn(r);
    return (uint32_t)__bfloat16_as_ushort(hb) | ((uint32_t)__bfloat16_as_ushort(lb) << 16);
}

// ---------------- tiny kernels ----------------
__global__ void zero_kernel() {
    if (threadIdx.x < E_EXP) g_cnt[threadIdx.x] = 0;
}

__global__ void router_kernel(const float* __restrict__ x,
                              const float* __restrict__ gw,
                              const float* __restrict__ bias) {
    __shared__ float xs[D_DIM];
    __shared__ float logits[E_EXP];
    int t = blockIdx.x;
    const float4* xr = (const float4*)(x + (size_t)t * D_DIM);
    for (int i = threadIdx.x; i < D_DIM / 4; i += blockDim.x)
        ((float4*)xs)[i] = xr[i];
    __syncthreads();

    int e = threadIdx.x >> 2;
    int g = threadIdx.x & 3;
    const float4* wrow = (const float4*)(gw + (size_t)e * D_DIM);
    float s = 0.f;
    for (int d4 = g; d4 < D_DIM / 4; d4 += 4) {
        float4 a = ((const float4*)xs)[d4];
        float4 b = wrow[d4];
        s += a.x * b.x + a.y * b.y + a.z * b.z + a.w * b.w;
    }
    s += __shfl_down_sync(0xffffffffu, s, 2, 4);
    s += __shfl_down_sync(0xffffffffu, s, 1, 4);
    if (g == 0) logits[e] = s + bias[e];
    __syncthreads();

    if (threadIdx.x == 0) {
        float v[TOPK]; int idx[TOPK];
        unsigned used = 0;
        for (int k = 0; k < TOPK; k++) {
            float best = -3.4e38f; int bi = 0;
            for (int j = 0; j < E_EXP; j++) {
                if (used & (1u << j)) continue;
                if (logits[j] > best) { best = logits[j]; bi = j; }
            }
            used |= 1u << bi; v[k] = best; idx[k] = bi;
        }
        float ex[TOPK], sum = 0.f;
        for (int k = 0; k < TOPK; k++) { ex[k] = __expf(v[k] - v[0]); sum += ex[k]; }
        float inv = 1.f / sum;
        for (int k = 0; k < TOPK; k++) {
            int ek = idx[k];
            int slot = atomicAdd(&g_cnt[ek], 1);
            g_pairs[ek * T_TOK + slot] = t * TOPK + k;
            g_w[t * TOPK + k] = ex[k] * inv;
        }
    }
}

// stats + compact work-list builder
__global__ void stats_kernel(float* __restrict__ tail) {
    int e = threadIdx.x;
    float c = (float)g_cnt[e];
    float mean = (float)(T_TOK * TOPK) / E_EXP;
    float d = c - mean;
    float v = d * d;
    for (int o = 16; o > 0; o >>= 1) v += __shfl_down_sync(0xffffffffu, v, o);
    if (tail) {
        tail[e] = c;
        if (e == 0) tail[E_EXP] = sqrtf(v / E_EXP) / (mean + 1e-6f);
    }
    if (threadIdx.x == 0) {
        int n = 0;
        for (int z = 0; z < E_EXP; ++z) {
            int tiles = (g_cnt[z] + 127) >> 7;
            for (int mt = 0; mt < tiles && n < MAXW; ++mt)
                g_work[n++] = (z << 16) | mt;
        }
        for (int mt = 0; mt < T_TOK / 128 && n < MAXW; ++mt)
            g_work[n++] = (E_EXP << 16) | mt;
        g_nwork = n;
    }
}

// ================= gate+up warp-MMA (R8 geometry, term-major MMA order) =================
// CTA 128M x 64N(F), 512 threads, 16 warps: 8 gate + 8 up, each 32x32. BK=64.
#define APITCH 144
#define GU_A_HI 0
#define GU_A_LO 18432
#define GU_BG_HI 36864
#define GU_BG_LO 46080
#define GU_BU_HI 55296
#define GU_BU_LO 64512
#define GU_STAGE 73728
#define GU_SMEM (1024 + 2 * GU_STAGE)   // 148480

__global__ void __launch_bounds__(512, 1)
gu_mma(const float* __restrict__ x,
       const float* __restrict__ Wg, const float* __restrict__ Wu,
       const float* __restrict__ wsg, const float* __restrict__ wsu) {
    extern __shared__ char smem[];
    int tid = threadIdx.x;
    int wi = blockIdx.y;
    if (wi >= g_nwork) return;
    int code = g_work[wi];
    int z = code >> 16;
    int mt = code & 0xffff;
    bool SH = (z == E_EXP);
    int ne = SH ? T_TOK : g_cnt[z];
    int m0 = mt * 128;
    int n0 = blockIdx.x * 64;
    const float* wgp = SH ? wsg : (Wg + (size_t)z * F_DIM * D_DIM);
    const float* wup = SH ? wsu : (Wu + (size_t)z * F_DIM * D_DIM);

    int* s_pair = (int*)smem;
    int* s_src  = (int*)(smem + 512);
    if (tid < 128) {
        int m = m0 + tid;
        int pair = SH ? m : ((m < ne) ? g_pairs[z * T_TOK + m] : g_pairs[z * T_TOK]);
        s_pair[tid] = pair;
        s_src[tid]  = SH ? m : (pair >> 2);
    }
    __syncthreads();

    const int c4 = tid & 15;       // float4 column within K-chunk
    const int rb = tid >> 4;       // base row (0..31)

    const float* aptr[4];
#pragma unroll
    for (int j = 0; j < 4; ++j)
        aptr[j] = x + (size_t)s_src[rb + 32 * j] * D_DIM + c4 * 4;
    const float* gptr[2];
    const float* uptr[2];
#pragma unroll
    for (int j = 0; j < 2; ++j) {
        gptr[j] = wgp + (size_t)(n0 + rb + 32 * j) * D_DIM + c4 * 4;
        uptr[j] = wup + (size_t)(n0 + rb + 32 * j) * D_DIM + c4 * 4;
    }

    const int wid = tid >> 5, lane = tid & 31;
    const bool isUp = wid >= 8;
    const int q = wid & 7;
    const int wm = q >> 1, wn = q & 1;   // warp: rows wm*32, cols wn*32

    float acc[2][4][4] = {};

    float4 ra[4], rg[2], ru[2];
#pragma unroll
    for (int j = 0; j < 4; ++j) ra[j] = *(const float4*)(aptr[j]);
#pragma unroll
    for (int j = 0; j < 2; ++j) { rg[j] = *(const float4*)(gptr[j]); ru[j] = *(const float4*)(uptr[j]); }

    const uint32_t a_row = wm * 32 + (lane & 15);
    const uint32_t a_colb = (lane >> 4) * 16;
    const uint32_t b_row = wn * 32 + ((lane >> 3) >> 1) * 8 + (lane & 7);
    const uint32_t b_colb = ((lane >> 3) & 1) * 16;

#define GU_STORE(BUF) do { \
    char* p; \
    _Pragma("unroll") \
    for (int j = 0; j < 4; ++j) { \
        p = (BUF) + (rb + 32 * j) * APITCH + c4 * 8; \
        split_store4(p + GU_A_HI, p + GU_A_LO, ra[j]); \
    } \
    _Pragma("unroll") \
    for (int j = 0; j < 2; ++j) { \
        p = (BUF) + (rb + 32 * j) * APITCH + c4 * 8; \
        split_store4(p + GU_BG_HI, p + GU_BG_LO, rg[j]); \
        split_store4(p + GU_BU_HI, p + GU_BU_LO, ru[j]); \
    } \
} while (0)

    GU_STORE(smem + 1024);
    __syncthreads();

    for (int ch = 0; ch < 16; ++ch) {
        if (ch < 15) {
            int k0 = (ch + 1) * 64;
#pragma unroll
            for (int j = 0; j < 4; ++j) ra[j] = *(const float4*)(aptr[j] + k0);
#pragma unroll
            for (int j = 0; j < 2; ++j) { rg[j] = *(const float4*)(gptr[j] + k0); ru[j] = *(const float4*)(uptr[j] + k0); }
        }
        {
            char* cur = smem + 1024 + (ch & 1) * GU_STAGE;
            uint32_t abase = smem_u32(cur) + GU_A_HI;
            uint32_t bbase = smem_u32(cur) + (isUp ? GU_BU_HI : GU_BG_HI);
#pragma unroll
            for (int ks = 0; ks < 4; ++ks) {
                uint32_t koff = ks * 32;
                uint32_t ah[2][4], al[2][4];
#pragma unroll
                for (int mt2 = 0; mt2 < 2; ++mt2) {
                    uint32_t ad = abase + (a_row + mt2 * 16) * APITCH + koff + a_colb;
                    ldm4(ah[mt2], ad);
                    ldm4(al[mt2], ad + (GU_A_LO - GU_A_HI));
                }
                uint32_t bh[8], bl[8];
#pragma unroll
                for (int p2 = 0; p2 < 2; ++p2) {
                    uint32_t bd = bbase + (b_row + p2 * 16) * APITCH + koff + b_colb;
                    ldm4(&bh[p2 * 4], bd);
                    ldm4(&bl[p2 * 4], bd + (GU_BG_LO - GU_BG_HI));
                }
                // term-major order: 8 independent accumulators between same-acc reuse
#pragma unroll
                for (int mt2 = 0; mt2 < 2; ++mt2)
#pragma unroll
                    for (int nt = 0; nt < 4; ++nt)
                        mma16816(acc[mt2][nt], ah[mt2], &bh[nt * 2]);
#pragma unroll
                for (int mt2 = 0; mt2 < 2; ++mt2)
#pragma unroll
                    for (int nt = 0; nt < 4; ++nt)
                        mma16816(acc[mt2][nt], ah[mt2], &bl[nt * 2]);
#pragma unroll
                for (int mt2 = 0; mt2 < 2; ++mt2)
#pragma unroll
                    for (int nt = 0; nt < 4; ++nt)
                        mma16816(acc[mt2][nt], al[mt2], &bh[nt * 2]);
            }
        }
        if (ch < 15) {
            char* nxt = smem + 1024 + ((ch + 1) & 1) * GU_STAGE;
            GU_STORE(nxt);
            __syncthreads();
        }
    }
    __syncthreads();

    // epilogue: stage gate+up fp32, silu, pack, store
    float* stg_g = (float*)(smem + 1024);
    float* stg_u = stg_g + 128 * 66;
    float* mystg = isUp ? stg_u : stg_g;
#pragma unroll
    for (int mt2 = 0; mt2 < 2; ++mt2)
#pragma unroll
        for (int nt = 0; nt < 4; ++nt) {
            int r = wm * 32 + mt2 * 16 + (lane >> 2);
            int c = wn * 32 + nt * 8 + (lane & 3) * 2;
            *(float2*)&mystg[r * 66 + c]       = make_float2(acc[mt2][nt][0], acc[mt2][nt][1]);
            *(float2*)&mystg[(r + 8) * 66 + c] = make_float2(acc[mt2][nt][2], acc[mt2][nt][3]);
        }
    __syncthreads();

    uint32_t* dst = SH ? g_hsp : g_hp;
    {
        int r = tid >> 2;
        int c0 = (tid & 3) * 16;
        uint32_t* drow = dst + (size_t)s_pair[r] * F_DIM + n0 + c0;
#pragma unroll
        for (int jj = 0; jj < 16; jj += 4) {
            uint4 o;
            uint32_t* po = &o.x;
#pragma unroll
            for (int k = 0; k < 4; ++k) {
                float gg = stg_g[r * 66 + c0 + jj + k];
                float uu = stg_u[r * 66 + c0 + jj + k];
                float h = gg / (1.f + __expf(-gg)) * uu;
                po[k] = pack_split1(h);
            }
            *(uint4*)(drow + jj) = o;
        }
    }
}

// ================= down warp-MMA (R8 geometry, term-major MMA order) =================
// CTA 128M x 128N(D), 512 threads, 16 warps of 32x32 (4x4). BK=64 over F.
#define DN_A_HI 0
#define DN_A_LO 18432
#define DN_B_HI 36864
#define DN_B_LO 55296
#define DN_STAGE 73728
#define DN_SMEM (1024 + 2 * DN_STAGE)   // 148480

__global__ void __launch_bounds__(512, 1)
dn_mma(const float* __restrict__ Wd, const float* __restrict__ wsd,
       float* __restrict__ out) {
    extern __shared__ char smem[];
    int tid = threadIdx.x;
    int wi = blockIdx.y;
    if (wi >= g_nwork) return;
    int code = g_work[wi];
    int z = code >> 16;
    int mt = code & 0xffff;
    bool SH = (z == E_EXP);
    int ne = SH ? T_TOK : g_cnt[z];
    int m0 = mt * 128;
    int n0 = blockIdx.x * 128;
    const float* wdp = SH ? wsd : (Wd + (size_t)z * D_DIM * F_DIM);
    const uint32_t* hsrc = SH ? g_hsp : g_hp;

    int* s_pair = (int*)smem;
    if (tid < 128) {
        int m = m0 + tid;
        s_pair[tid] = SH ? m : ((m < ne) ? g_pairs[z * T_TOK + m] : g_pairs[z * T_TOK]);
    }
    __syncthreads();

    const int c4 = tid & 15;
    const int rb = tid >> 4;

    const uint32_t* aptr[4];
#pragma unroll
    for (int j = 0; j < 4; ++j)
        aptr[j] = hsrc + (size_t)s_pair[rb + 32 * j] * F_DIM + c4 * 4;
    const float* bptr[4];
#pragma unroll
    for (int j = 0; j < 4; ++j)
        bptr[j] = wdp + (size_t)(n0 + rb + 32 * j) * F_DIM + c4 * 4;

    const int wid = tid >> 5, lane = tid & 31;
    const int wm = wid >> 2, wn = wid & 3;   // rows wm*32, cols wn*32

    float acc[2][4][4] = {};

    uint4  rha[4];
    float4 rwb[4];
#pragma unroll
    for (int j = 0; j < 4; ++j) rha[j] = *(const uint4*)(aptr[j]);
#pragma unroll
    for (int j = 0; j < 4; ++j) rwb[j] = *(const float4*)(bptr[j]);

    const uint32_t a_row = wm * 32 + (lane & 15);
    const uint32_t a_colb = (lane >> 4) * 16;
    const uint32_t b_row = wn * 32 + ((lane >> 3) >> 1) * 8 + (lane & 7);
    const uint32_t b_colb = ((lane >> 3) & 1) * 16;

#define DN_STORE(BUF) do { \
    char* p; \
    _Pragma("unroll") \
    for (int j = 0; j < 4; ++j) { \
        p = (BUF) + (rb + 32 * j) * APITCH + c4 * 8; \
        uint32_t h0 = __byte_perm(rha[j].x, rha[j].y, 0x5410); \
        uint32_t h1 = __byte_perm(rha[j].z, rha[j].w, 0x5410); \
        uint32_t l0 = __byte_perm(rha[j].x, rha[j].y, 0x7632); \
        uint32_t l1 = __byte_perm(rha[j].z, rha[j].w, 0x7632); \
        *(uint2*)(p + DN_A_HI) = make_uint2(h0, h1); \
        *(uint2*)(p + DN_A_LO) = make_uint2(l0, l1); \
    } \
    _Pragma("unroll") \
    for (int j = 0; j < 4; ++j) { \
        p = (BUF) + (rb + 32 * j) * APITCH + c4 * 8; \
        split_store4(p + DN_B_HI, p + DN_B_LO, rwb[j]); \
    } \
} while (0)

    DN_STORE(smem + 1024);
    __syncthreads();

    for (int ch = 0; ch < 32; ++ch) {
        if (ch < 31) {
            int k0 = (ch + 1) * 64;
#pragma unroll
            for (int j = 0; j < 4; ++j) rha[j] = *(const uint4*)(aptr[j] + k0);
#pragma unroll
            for (int j = 0; j < 4; ++j) rwb[j] = *(const float4*)(bptr[j] + k0);
        }
        {
            char* cur = smem + 1024 + (ch & 1) * DN_STAGE;
            uint32_t abase = smem_u32(cur) + DN_A_HI;
            uint32_t bbase = smem_u32(cur) + DN_B_HI;
#pragma unroll
            for (int ks = 0; ks < 4; ++ks) {
                uint32_t koff = ks * 32;
                uint32_t ah[2][4], al[2][4];
#pragma unroll
                for (int mt2 = 0; mt2 < 2; ++mt2) {
                    uint32_t ad = abase + (a_row + mt2 * 16) * APITCH + koff + a_colb;
                    ldm4(ah[mt2], ad);
                    ldm4(al[mt2], ad + (DN_A_LO - DN_A_HI));
                }
                uint32_t bh[8], bl[8];
#pragma unroll
                for (int p2 = 0; p2 < 2; ++p2) {
                    uint32_t bd = bbase + (b_row + p2 * 16) * APITCH + koff + b_colb;
                    ldm4(&bh[p2 * 4], bd);
                    ldm4(&bl[p2 * 4], bd + (DN_B_LO - DN_B_HI));
                }
                // term-major order
#pragma unroll
                for (int mt2 = 0; mt2 < 2; ++mt2)
#pragma unroll
                    for (int nt = 0; nt < 4; ++nt)
                        mma16816(acc[mt2][nt], ah[mt2], &bh[nt * 2]);
#pragma unroll
                for (int mt2 = 0; mt2 < 2; ++mt2)
#pragma unroll
                    for (int nt = 0; nt < 4; ++nt)
                        mma16816(acc[mt2][nt], ah[mt2], &bl[nt * 2]);
#pragma unroll
                for (int mt2 = 0; mt2 < 2; ++mt2)
#pragma unroll
                    for (int nt = 0; nt < 4; ++nt)
                        mma16816(acc[mt2][nt], al[mt2], &bh[nt * 2]);
            }
        }
        if (ch < 31) {
            char* nxt = smem + 1024 + ((ch + 1) & 1) * DN_STAGE;
            DN_STORE(nxt);
            __syncthreads();
        }
    }
    __syncthreads();

    float* stg = (float*)(smem + 1024);
#pragma unroll
    for (int mt2 = 0; mt2 < 2; ++mt2)
#pragma unroll
        for (int nt = 0; nt < 4; ++nt) {
            int r = wm * 32 + mt2 * 16 + (lane >> 2);
            int c = wn * 32 + nt * 8 + (lane & 3) * 2;
            *(float2*)&stg[r * 132 + c]       = make_float2(acc[mt2][nt][0], acc[mt2][nt][1]);
            *(float2*)&stg[(r + 8) * 132 + c] = make_float2(acc[mt2][nt][2], acc[mt2][nt][3]);
        }
    __syncthreads();

    {
        int r = tid >> 2;
        int c0 = (tid & 3) * 32;
        float* drow;
        if (SH) drow = out + (size_t)(m0 + r) * D_DIM + n0 + c0;
        else    drow = g_y + (size_t)s_pair[r] * D_DIM + n0 + c0;
#pragma unroll
        for (int jj = 0; jj < 32; jj += 4) {
            float4 v = make_float4(stg[r * 132 + c0 + jj], stg[r * 132 + c0 + jj + 1],
                                   stg[r * 132 + c0 + jj + 2], stg[r * 132 + c0 + jj + 3]);
            *(float4*)(drow + jj) = v;
        }
    }
}

// ================= combine: out += sum_k w_k * y_pair =================
__global__ void combine_kernel(float* __restrict__ out) {
    int t = blockIdx.x;
    int c = threadIdx.x * 4;
    float4 o = *(float4*)(out + (size_t)t * D_DIM + c);
#pragma unroll
    for (int k = 0; k < TOPK; ++k) {
        int pair = t * TOPK + k;
        float w = g_w[pair];
        float4 y = *(const float4*)(g_y + (size_t)pair * D_DIM + c);
        o.x += w * y.x; o.y += w * y.y; o.z += w * y.z; o.w += w * y.w;
    }
    *(float4*)(out + (size_t)t * D_DIM + c) = o;
}

// ---------------- launch ----------------
extern "C" void kernel_launch(void* const* d_in, const int* in_sizes, int n_in,
                              void* d_out, int out_size) {
    const float* x    = (const float*)d_in[0];
    const float* gw   = (const float*)d_in[1];
    const float* bias = (const float*)d_in[2];
    const float* wg   = (const float*)d_in[3];
    const float* wu   = (const float*)d_in[4];
    const float* wd   = (const float*)d_in[5];
    const float* wsg  = (const float*)d_in[6];
    const float* wsu  = (const float*)d_in[7];
    const float* wsd  = (const float*)d_in[8];
    float* out = (float*)d_out;

    static int attr_done = 0;
    if (!attr_done) {
        cudaFuncSetAttribute(gu_mma, cudaFuncAttributeMaxDynamicSharedMemorySize, GU_SMEM);
        cudaFuncSetAttribute(dn_mma, cudaFuncAttributeMaxDynamicSharedMemorySize, DN_SMEM);
        attr_done = 1;
    }

    zero_kernel<<<1, 32>>>();
    router_kernel<<<T_TOK, 128>>>(x, gw, bias);

    float* tail = (out_size >= T_TOK * D_DIM + E_EXP + 1) ? (out + T_TOK * D_DIM) : nullptr;
    stats_kernel<<<1, 32>>>(tail);

    // gate+up: compact work list (routed + shared)
    gu_mma<<<dim3(F_DIM / 64, MAXW), 512, GU_SMEM>>>(x, wg, wu, wsg, wsu);

    // down: compact work list (routed -> g_y, shared -> out)
    dn_mma<<<dim3(D_DIM / 128, MAXW), 512, DN_SMEM>>>(wd, wsd, out);

    // weighted combine
    combine_kernel<<<T_TOK, 256>>>(out);
}

// round 11
// speedup vs baseline: 2.0054x; 1.2824x over previous
#include <cuda_runtime.h>
#include <cuda_fp16.h>
#include <stdint.h>

#define T_TOK 1024
#define D_DIM 1024
#define F_DIM 2048
#define E_EXP 32
#define TOPK  4
#define NPAIR (T_TOK * TOPK)
#define MAXW  96

// ---------------- static scratch ----------------
__device__ int     g_cnt[E_EXP];
__device__ int     g_pairs[E_EXP * T_TOK];
__device__ float   g_w[NPAIR];
__device__ __half  g_hp[(size_t)NPAIR * F_DIM];    // routed hidden fp16 (17MB)
__device__ __half  g_hsp[(size_t)T_TOK * F_DIM];   // shared hidden fp16 (4MB)
__device__ float   g_y[(size_t)NPAIR * D_DIM];     // routed per-pair down output
__device__ int     g_nwork;
__device__ int     g_work[MAXW];                   // (z<<16)|mt ; z==E_EXP -> shared

// ---------------- helpers ----------------
__device__ __forceinline__ uint32_t smem_u32(const void* p) {
    uint32_t a;
    asm("{ .reg .u64 t; cvta.to.shared.u64 t, %1; cvt.u32.u64 %0, t; }" : "=r"(a) : "l"(p));
    return a;
}
__device__ __forceinline__ void ldm4(uint32_t* r, uint32_t addr) {
    asm volatile("ldmatrix.sync.aligned.m8n8.x4.shared.b16 {%0,%1,%2,%3}, [%4];"
                 : "=r"(r[0]), "=r"(r[1]), "=r"(r[2]), "=r"(r[3]) : "r"(addr));
}
__device__ __forceinline__ void mma16816(float* d, const uint32_t* a, const uint32_t* b) {
    asm volatile("mma.sync.aligned.m16n8k16.row.col.f32.f16.f16.f32 "
                 "{%0,%1,%2,%3}, {%4,%5,%6,%7}, {%8,%9}, {%0,%1,%2,%3};"
                 : "+f"(d[0]), "+f"(d[1]), "+f"(d[2]), "+f"(d[3])
                 : "r"(a[0]), "r"(a[1]), "r"(a[2]), "r"(a[3]), "r"(b[0]), "r"(b[1]));
}
__device__ __forceinline__ uint32_t h2bits(__half2 h) {
    return *reinterpret_cast<uint32_t*>(&h);
}
// fp16 split of two floats: hi = rn(x), lo = rn(x - hi)
__device__ __forceinline__ void cvt_split16(float x0, float x1, uint32_t& hi, uint32_t& lo) {
    __half2 h = __floats2half2_rn(x0, x1);
    hi = h2bits(h);
    float f0 = __half2float(__low2half(h));
    float f1 = __half2float(__high2half(h));
    __half2 l = __floats2half2_rn(x0 - f0, x1 - f1);
    lo = h2bits(l);
}
// split-store float4 -> hi tile + lo tile (8 bytes each)
__device__ __forceinline__ void split_store4(char* hi, char* lo, float4 v) {
    uint32_t h0, l0, h1, l1;
    cvt_split16(v.x, v.y, h0, l0);
    cvt_split16(v.z, v.w, h1, l1);
    *(uint2*)hi = make_uint2(h0, h1);
    *(uint2*)lo = make_uint2(l0, l1);
}
// hi-only store float4 -> 8 bytes fp16
__device__ __forceinline__ void h16_store4(char* dst, float4 v) {
    __half2 a = __floats2half2_rn(v.x, v.y);
    __half2 b = __floats2half2_rn(v.z, v.w);
    *(uint2*)dst = make_uint2(h2bits(a), h2bits(b));
}

// ---------------- tiny kernels ----------------
__global__ void zero_kernel() {
    if (threadIdx.x < E_EXP) g_cnt[threadIdx.x] = 0;
}

__global__ void router_kernel(const float* __restrict__ x,
                              const float* __restrict__ gw,
                              const float* __restrict__ bias) {
    __shared__ float xs[D_DIM];
    __shared__ float logits[E_EXP];
    int t = blockIdx.x;
    const float4* xr = (const float4*)(x + (size_t)t * D_DIM);
    for (int i = threadIdx.x; i < D_DIM / 4; i += blockDim.x)
        ((float4*)xs)[i] = xr[i];
    __syncthreads();

    int e = threadIdx.x >> 2;
    int g = threadIdx.x & 3;
    const float4* wrow = (const float4*)(gw + (size_t)e * D_DIM);
    float s = 0.f;
    for (int d4 = g; d4 < D_DIM / 4; d4 += 4) {
        float4 a = ((const float4*)xs)[d4];
        float4 b = wrow[d4];
        s += a.x * b.x + a.y * b.y + a.z * b.z + a.w * b.w;
    }
    s += __shfl_down_sync(0xffffffffu, s, 2, 4);
    s += __shfl_down_sync(0xffffffffu, s, 1, 4);
    if (g == 0) logits[e] = s + bias[e];
    __syncthreads();

    if (threadIdx.x == 0) {
        float v[TOPK]; int idx[TOPK];
        unsigned used = 0;
        for (int k = 0; k < TOPK; k++) {
            float best = -3.4e38f; int bi = 0;
            for (int j = 0; j < E_EXP; j++) {
                if (used & (1u << j)) continue;
                if (logits[j] > best) { best = logits[j]; bi = j; }
            }
            used |= 1u << bi; v[k] = best; idx[k] = bi;
        }
        float ex[TOPK], sum = 0.f;
        for (int k = 0; k < TOPK; k++) { ex[k] = __expf(v[k] - v[0]); sum += ex[k]; }
        float inv = 1.f / sum;
        for (int k = 0; k < TOPK; k++) {
            int ek = idx[k];
            int slot = atomicAdd(&g_cnt[ek], 1);
            g_pairs[ek * T_TOK + slot] = t * TOPK + k;
            g_w[t * TOPK + k] = ex[k] * inv;
        }
    }
}

// stats + compact work-list builder
__global__ void stats_kernel(float* __restrict__ tail) {
    int e = threadIdx.x;
    float c = (float)g_cnt[e];
    float mean = (float)(T_TOK * TOPK) / E_EXP;
    float d = c - mean;
    float v = d * d;
    for (int o = 16; o > 0; o >>= 1) v += __shfl_down_sync(0xffffffffu, v, o);
    if (tail) {
        tail[e] = c;
        if (e == 0) tail[E_EXP] = sqrtf(v / E_EXP) / (mean + 1e-6f);
    }
    if (threadIdx.x == 0) {
        int n = 0;
        for (int z = 0; z < E_EXP; ++z) {
            int tiles = (g_cnt[z] + 127) >> 7;
            for (int mt = 0; mt < tiles && n < MAXW; ++mt)
                g_work[n++] = (z << 16) | mt;
        }
        for (int mt = 0; mt < T_TOK / 128 && n < MAXW; ++mt)
            g_work[n++] = (E_EXP << 16) | mt;
        g_nwork = n;
    }
}

// ================= gate+up warp-MMA (fp16 2-term) =================
// CTA 128M x 64N(F), 512 threads, 16 warps: 8 gate + 8 up, each 32x32. BK=64.
#define APITCH 144
#define GU_A_HI 0
#define GU_BG_HI 18432
#define GU_BG_LO 27648
#define GU_BU_HI 36864
#define GU_BU_LO 46080
#define GU_STAGE 55296
#define GU_SMEM (1024 + 2 * GU_STAGE)   // 111616

__global__ void __launch_bounds__(512, 1)
gu_mma(const float* __restrict__ x,
       const float* __restrict__ Wg, const float* __restrict__ Wu,
       const float* __restrict__ wsg, const float* __restrict__ wsu) {
    extern __shared__ char smem[];
    int tid = threadIdx.x;
    int wi = blockIdx.y;
    if (wi >= g_nwork) return;
    int code = g_work[wi];
    int z = code >> 16;
    int mt = code & 0xffff;
    bool SH = (z == E_EXP);
    int ne = SH ? T_TOK : g_cnt[z];
    int m0 = mt * 128;
    int n0 = blockIdx.x * 64;
    const float* wgp = SH ? wsg : (Wg + (size_t)z * F_DIM * D_DIM);
    const float* wup = SH ? wsu : (Wu + (size_t)z * F_DIM * D_DIM);

    int* s_pair = (int*)smem;
    int* s_src  = (int*)(smem + 512);
    if (tid < 128) {
        int m = m0 + tid;
        int pair = SH ? m : ((m < ne) ? g_pairs[z * T_TOK + m] : g_pairs[z * T_TOK]);
        s_pair[tid] = pair;
        s_src[tid]  = SH ? m : (pair >> 2);
    }
    __syncthreads();

    const int c4 = tid & 15;       // float4 column within K-chunk
    const int rb = tid >> 4;       // base row (0..31)

    const float* aptr[4];
#pragma unroll
    for (int j = 0; j < 4; ++j)
        aptr[j] = x + (size_t)s_src[rb + 32 * j] * D_DIM + c4 * 4;
    const float* gptr[2];
    const float* uptr[2];
#pragma unroll
    for (int j = 0; j < 2; ++j) {
        gptr[j] = wgp + (size_t)(n0 + rb + 32 * j) * D_DIM + c4 * 4;
        uptr[j] = wup + (size_t)(n0 + rb + 32 * j) * D_DIM + c4 * 4;
    }

    const int wid = tid >> 5, lane = tid & 31;
    const bool isUp = wid >= 8;
    const int q = wid & 7;
    const int wm = q >> 1, wn = q & 1;   // warp: rows wm*32, cols wn*32

    float acc[2][4][4] = {};

    float4 ra[4], rg[2], ru[2];
#pragma unroll
    for (int j = 0; j < 4; ++j) ra[j] = *(const float4*)(aptr[j]);
#pragma unroll
    for (int j = 0; j < 2; ++j) { rg[j] = *(const float4*)(gptr[j]); ru[j] = *(const float4*)(uptr[j]); }

    const uint32_t a_row = wm * 32 + (lane & 15);
    const uint32_t a_colb = (lane >> 4) * 16;
    const uint32_t b_row = wn * 32 + ((lane >> 3) >> 1) * 8 + (lane & 7);
    const uint32_t b_colb = ((lane >> 3) & 1) * 16;

#define GU_STORE(BUF) do { \
    char* p; \
    _Pragma("unroll") \
    for (int j = 0; j < 4; ++j) { \
        p = (BUF) + (rb + 32 * j) * APITCH + c4 * 8; \
        h16_store4(p + GU_A_HI, ra[j]); \
    } \
    _Pragma("unroll") \
    for (int j = 0; j < 2; ++j) { \
        p = (BUF) + (rb + 32 * j) * APITCH + c4 * 8; \
        split_store4(p + GU_BG_HI, p + GU_BG_LO, rg[j]); \
        split_store4(p + GU_BU_HI, p + GU_BU_LO, ru[j]); \
    } \
} while (0)

    GU_STORE(smem + 1024);
    __syncthreads();

    for (int ch = 0; ch < 16; ++ch) {
        if (ch < 15) {
            int k0 = (ch + 1) * 64;
#pragma unroll
            for (int j = 0; j < 4; ++j) ra[j] = *(const float4*)(aptr[j] + k0);
#pragma unroll
            for (int j = 0; j < 2; ++j) { rg[j] = *(const float4*)(gptr[j] + k0); ru[j] = *(const float4*)(uptr[j] + k0); }
        }
        {
            char* cur = smem + 1024 + (ch & 1) * GU_STAGE;
            uint32_t abase = smem_u32(cur) + GU_A_HI;
            uint32_t bbase = smem_u32(cur) + (isUp ? GU_BU_HI : GU_BG_HI);
#pragma unroll
            for (int ks = 0; ks < 4; ++ks) {
                uint32_t koff = ks * 32;
                uint32_t ah[2][4];
#pragma unroll
                for (int mt2 = 0; mt2 < 2; ++mt2) {
                    uint32_t ad = abase + (a_row + mt2 * 16) * APITCH + koff + a_colb;
                    ldm4(ah[mt2], ad);
                }
                uint32_t bh[8], bl[8];
#pragma unroll
                for (int p2 = 0; p2 < 2; ++p2) {
                    uint32_t bd = bbase + (b_row + p2 * 16) * APITCH + koff + b_colb;
                    ldm4(&bh[p2 * 4], bd);
                    ldm4(&bl[p2 * 4], bd + (GU_BG_LO - GU_BG_HI));
                }
                // 2-term fp16: Ah*Bh + Ah*Bl (term-major for ILP)
#pragma unroll
                for (int mt2 = 0; mt2 < 2; ++mt2)
#pragma unroll
                    for (int nt = 0; nt < 4; ++nt)
                        mma16816(acc[mt2][nt], ah[mt2], &bh[nt * 2]);
#pragma unroll
                for (int mt2 = 0; mt2 < 2; ++mt2)
#pragma unroll
                    for (int nt = 0; nt < 4; ++nt)
                        mma16816(acc[mt2][nt], ah[mt2], &bl[nt * 2]);
            }
        }
        if (ch < 15) {
            char* nxt = smem + 1024 + ((ch + 1) & 1) * GU_STAGE;
            GU_STORE(nxt);
            __syncthreads();
        }
    }
    __syncthreads();

    // epilogue: stage gate+up fp32, silu, store fp16 h
    float* stg_g = (float*)(smem + 1024);
    float* stg_u = stg_g + 128 * 66;
    float* mystg = isUp ? stg_u : stg_g;
#pragma unroll
    for (int mt2 = 0; mt2 < 2; ++mt2)
#pragma unroll
        for (int nt = 0; nt < 4; ++nt) {
            int r = wm * 32 + mt2 * 16 + (lane >> 2);
            int c = wn * 32 + nt * 8 + (lane & 3) * 2;
            *(float2*)&mystg[r * 66 + c]       = make_float2(acc[mt2][nt][0], acc[mt2][nt][1]);
            *(float2*)&mystg[(r + 8) * 66 + c] = make_float2(acc[mt2][nt][2], acc[mt2][nt][3]);
        }
    __syncthreads();

    __half* dst = SH ? g_hsp : g_hp;
    {
        int r = tid >> 2;
        int c0 = (tid & 3) * 16;
        __half* drow = dst + (size_t)s_pair[r] * F_DIM + n0 + c0;
#pragma unroll
        for (int jj = 0; jj < 16; jj += 8) {
            uint4 o;
            uint32_t* po = &o.x;
#pragma unroll
            for (int k = 0; k < 4; ++k) {
                float g0 = stg_g[r * 66 + c0 + jj + 2 * k];
                float g1 = stg_g[r * 66 + c0 + jj + 2 * k + 1];
                float u0 = stg_u[r * 66 + c0 + jj + 2 * k];
                float u1 = stg_u[r * 66 + c0 + jj + 2 * k + 1];
                float h0 = g0 / (1.f + __expf(-g0)) * u0;
                float h1 = g1 / (1.f + __expf(-g1)) * u1;
                __half2 ph = __floats2half2_rn(h0, h1);
                po[k] = h2bits(ph);
            }
            *(uint4*)(drow + jj) = o;
        }
    }
}

// ================= down warp-MMA (fp16 2-term) =================
// CTA 128M x 128N(D), 512 threads, 16 warps of 32x32 (4x4). BK=64 over F.
#define DN_A 0
#define DN_B_HI 18432
#define DN_B_LO 36864
#define DN_STAGE 55296
#define DN_SMEM (1024 + 2 * DN_STAGE)   // 111616

__global__ void __launch_bounds__(512, 1)
dn_mma(const float* __restrict__ Wd, const float* __restrict__ wsd,
       float* __restrict__ out) {
    extern __shared__ char smem[];
    int tid = threadIdx.x;
    int wi = blockIdx.y;
    if (wi >= g_nwork) return;
    int code = g_work[wi];
    int z = code >> 16;
    int mt = code & 0xffff;
    bool SH = (z == E_EXP);
    int ne = SH ? T_TOK : g_cnt[z];
    int m0 = mt * 128;
    int n0 = blockIdx.x * 128;
    const float* wdp = SH ? wsd : (Wd + (size_t)z * D_DIM * F_DIM);
    const __half* hsrc = SH ? g_hsp : g_hp;

    int* s_pair = (int*)smem;
    if (tid < 128) {
        int m = m0 + tid;
        s_pair[tid] = SH ? m : ((m < ne) ? g_pairs[z * T_TOK + m] : g_pairs[z * T_TOK]);
    }
    __syncthreads();

    // A loader: fp16 source, 128 rows x 128B per chunk -> 1024 uint4, 2/thread
    const __half* haptr[2];
    unsigned soA[2];
#pragma unroll
    for (int j = 0; j < 2; ++j) {
        int idx = tid + 512 * j;
        int row = idx >> 3, c8 = idx & 7;
        haptr[j] = hsrc + (size_t)s_pair[row] * F_DIM + c8 * 8;
        soA[j]   = row * APITCH + c8 * 16;
    }
    // B loader: fp32 source, 128 rows x 16 f4 -> 4/thread
    const int c4 = tid & 15;
    const int rbB = tid >> 4;
    const float* bptr[4];
#pragma unroll
    for (int j = 0; j < 4; ++j)
        bptr[j] = wdp + (size_t)(n0 + rbB + 32 * j) * F_DIM + c4 * 4;

    const int wid = tid >> 5, lane = tid & 31;
    const int wm = wid >> 2, wn = wid & 3;   // rows wm*32, cols wn*32

    float acc[2][4][4] = {};

    uint4  rha[2];
    float4 rwb[4];
#pragma unroll
    for (int j = 0; j < 2; ++j) rha[j] = *(const uint4*)(haptr[j]);
#pragma unroll
    for (int j = 0; j < 4; ++j) rwb[j] = *(const float4*)(bptr[j]);

    const uint32_t a_row = wm * 32 + (lane & 15);
    const uint32_t a_colb = (lane >> 4) * 16;
    const uint32_t b_row = wn * 32 + ((lane >> 3) >> 1) * 8 + (lane & 7);
    const uint32_t b_colb = ((lane >> 3) & 1) * 16;

#define DN_STORE(BUF) do { \
    char* b_ = (BUF); \
    _Pragma("unroll") \
    for (int j = 0; j < 2; ++j) \
        *(uint4*)(b_ + DN_A + soA[j]) = rha[j]; \
    _Pragma("unroll") \
    for (int j = 0; j < 4; ++j) { \
        char* p = b_ + (rbB + 32 * j) * APITCH + c4 * 8; \
        split_store4(p + DN_B_HI, p + DN_B_LO, rwb[j]); \
    } \
} while (0)

    DN_STORE(smem + 1024);
    __syncthreads();

    for (int ch = 0; ch < 32; ++ch) {
        if (ch < 31) {
            int k0 = (ch + 1) * 64;
#pragma unroll
            for (int j = 0; j < 2; ++j) rha[j] = *(const uint4*)(haptr[j] + k0);
#pragma unroll
            for (int j = 0; j < 4; ++j) rwb[j] = *(const float4*)(bptr[j] + k0);
        }
        {
            char* cur = smem + 1024 + (ch & 1) * DN_STAGE;
            uint32_t abase = smem_u32(cur) + DN_A;
            uint32_t bbase = smem_u32(cur) + DN_B_HI;
#pragma unroll
            for (int ks = 0; ks < 4; ++ks) {
                uint32_t koff = ks * 32;
                uint32_t ah[2][4];
#pragma unroll
                for (int mt2 = 0; mt2 < 2; ++mt2) {
                    uint32_t ad = abase + (a_row + mt2 * 16) * APITCH + koff + a_colb;
                    ldm4(ah[mt2], ad);
                }
                uint32_t bh[8], bl[8];
#pragma unroll
                for (int p2 = 0; p2 < 2; ++p2) {
                    uint32_t bd = bbase + (b_row + p2 * 16) * APITCH + koff + b_colb;
                    ldm4(&bh[p2 * 4], bd);
                    ldm4(&bl[p2 * 4], bd + (DN_B_LO - DN_B_HI));
                }
#pragma unroll
                for (int mt2 = 0; mt2 < 2; ++mt2)
#pragma unroll
                    for (int nt = 0; nt < 4; ++nt)
                        mma16816(acc[mt2][nt], ah[mt2], &bh[nt * 2]);
#pragma unroll
                for (int mt2 = 0; mt2 < 2; ++mt2)
#pragma unroll
                    for (int nt = 0; nt < 4; ++nt)
                        mma16816(acc[mt2][nt], ah[mt2], &bl[nt * 2]);
            }
        }
        if (ch < 31) {
            char* nxt = smem + 1024 + ((ch + 1) & 1) * DN_STAGE;
            DN_STORE(nxt);
            __syncthreads();
        }
    }
    __syncthreads();

    float* stg = (float*)(smem + 1024);
#pragma unroll
    for (int mt2 = 0; mt2 < 2; ++mt2)
#pragma unroll
        for (int nt = 0; nt < 4; ++nt) {
            int r = wm * 32 + mt2 * 16 + (lane >> 2);
            int c = wn * 32 + nt * 8 + (lane & 3) * 2;
            *(float2*)&stg[r * 132 + c]       = make_float2(acc[mt2][nt][0], acc[mt2][nt][1]);
            *(float2*)&stg[(r + 8) * 132 + c] = make_float2(acc[mt2][nt][2], acc[mt2][nt][3]);
        }
    __syncthreads();

    {
        int r = tid >> 2;
        int c0 = (tid & 3) * 32;
        float* drow;
        if (SH) drow = out + (size_t)(m0 + r) * D_DIM + n0 + c0;
        else    drow = g_y + (size_t)s_pair[r] * D_DIM + n0 + c0;
#pragma unroll
        for (int jj = 0; jj < 32; jj += 4) {
            float4 v = make_float4(stg[r * 132 + c0 + jj], stg[r * 132 + c0 + jj + 1],
                                   stg[r * 132 + c0 + jj + 2], stg[r * 132 + c0 + jj + 3]);
            *(float4*)(drow + jj) = v;
        }
    }
}

// ================= combine: out += sum_k w_k * y_pair =================
__global__ void combine_kernel(float* __restrict__ out) {
    int t = blockIdx.x;
    int c = threadIdx.x * 4;
    float4 o = *(float4*)(out + (size_t)t * D_DIM + c);
#pragma unroll
    for (int k = 0; k < TOPK; ++k) {
        int pair = t * TOPK + k;
        float w = g_w[pair];
        float4 y = *(const float4*)(g_y + (size_t)pair * D_DIM + c);
        o.x += w * y.x; o.y += w * y.y; o.z += w * y.z; o.w += w * y.w;
    }
    *(float4*)(out + (size_t)t * D_DIM + c) = o;
}

// ---------------- launch ----------------
extern "C" void kernel_launch(void* const* d_in, const int* in_sizes, int n_in,
                              void* d_out, int out_size) {
    const float* x    = (const float*)d_in[0];
    const float* gw   = (const float*)d_in[1];
    const float* bias = (const float*)d_in[2];
    const float* wg   = (const float*)d_in[3];
    const float* wu   = (const float*)d_in[4];
    const float* wd   = (const float*)d_in[5];
    const float* wsg  = (const float*)d_in[6];
    const float* wsu  = (const float*)d_in[7];
    const float* wsd  = (const float*)d_in[8];
    float* out = (float*)d_out;

    static int attr_done = 0;
    if (!attr_done) {
        cudaFuncSetAttribute(gu_mma, cudaFuncAttributeMaxDynamicSharedMemorySize, GU_SMEM);
        cudaFuncSetAttribute(dn_mma, cudaFuncAttributeMaxDynamicSharedMemorySize, DN_SMEM);
        attr_done = 1;
    }

    zero_kernel<<<1, 32>>>();
    router_kernel<<<T_TOK, 128>>>(x, gw, bias);

    float* tail = (out_size >= T_TOK * D_DIM + E_EXP + 1) ? (out + T_TOK * D_DIM) : nullptr;
    stats_kernel<<<1, 32>>>(tail);

    // gate+up: compact work list (routed + shared)
    gu_mma<<<dim3(F_DIM / 64, MAXW), 512, GU_SMEM>>>(x, wg, wu, wsg, wsu);

    // down: compact work list (routed -> g_y, shared -> out)
    dn_mma<<<dim3(D_DIM / 128, MAXW), 512, DN_SMEM>>>(wd, wsd, out);

    // weighted combine
    combine_kernel<<<T_TOK, 256>>>(out);
}

// round 12
// speedup vs baseline: 2.1176x; 1.0560x over previous
#include <cuda_runtime.h>
#include <cuda_fp16.h>
#include <stdint.h>

#define T_TOK 1024
#define D_DIM 1024
#define F_DIM 2048
#define E_EXP 32
#define TOPK  4
#define NPAIR (T_TOK * TOPK)
#define MAXW  96

// ---------------- static scratch ----------------
__device__ int     g_cnt[E_EXP];
__device__ int     g_pairs[E_EXP * T_TOK];
__device__ float   g_w[NPAIR];
__device__ __half  g_hp[(size_t)NPAIR * F_DIM];    // routed hidden fp16
__device__ __half  g_hsp[(size_t)T_TOK * F_DIM];   // shared hidden fp16
__device__ float   g_y[(size_t)NPAIR * D_DIM];     // routed per-pair down output
__device__ int     g_nwork;
__device__ int     g_work[MAXW];                   // (z<<16)|mt ; z==E_EXP -> shared

// ---------------- helpers ----------------
__device__ __forceinline__ uint32_t smem_u32(const void* p) {
    uint32_t a;
    asm("{ .reg .u64 t; cvta.to.shared.u64 t, %1; cvt.u32.u64 %0, t; }" : "=r"(a) : "l"(p));
    return a;
}
__device__ __forceinline__ void ldm4(uint32_t* r, uint32_t addr) {
    asm volatile("ldmatrix.sync.aligned.m8n8.x4.shared.b16 {%0,%1,%2,%3}, [%4];"
                 : "=r"(r[0]), "=r"(r[1]), "=r"(r[2]), "=r"(r[3]) : "r"(addr));
}
__device__ __forceinline__ void mma16816(float* d, const uint32_t* a, const uint32_t* b) {
    asm volatile("mma.sync.aligned.m16n8k16.row.col.f32.f16.f16.f32 "
                 "{%0,%1,%2,%3}, {%4,%5,%6,%7}, {%8,%9}, {%0,%1,%2,%3};"
                 : "+f"(d[0]), "+f"(d[1]), "+f"(d[2]), "+f"(d[3])
                 : "r"(a[0]), "r"(a[1]), "r"(a[2]), "r"(a[3]), "r"(b[0]), "r"(b[1]));
}
__device__ __forceinline__ uint32_t h2bits(__half2 h) {
    return *reinterpret_cast<uint32_t*>(&h);
}
// fp16 split of two floats: hi = rn(x), lo = rn(x - hi)
__device__ __forceinline__ void cvt_split16(float x0, float x1, uint32_t& hi, uint32_t& lo) {
    __half2 h = __floats2half2_rn(x0, x1);
    hi = h2bits(h);
    float f0 = __half2float(__low2half(h));
    float f1 = __half2float(__high2half(h));
    __half2 l = __floats2half2_rn(x0 - f0, x1 - f1);
    lo = h2bits(l);
}
__device__ __forceinline__ void split_store4(char* hi, char* lo, float4 v) {
    uint32_t h0, l0, h1, l1;
    cvt_split16(v.x, v.y, h0, l0);
    cvt_split16(v.z, v.w, h1, l1);
    *(uint2*)hi = make_uint2(h0, h1);
    *(uint2*)lo = make_uint2(l0, l1);
}
__device__ __forceinline__ void h16_store4(char* dst, float4 v) {
    __half2 a = __floats2half2_rn(v.x, v.y);
    __half2 b = __floats2half2_rn(v.z, v.w);
    *(uint2*)dst = make_uint2(h2bits(a), h2bits(b));
}

// ---------------- tiny kernels ----------------
__global__ void zero_kernel() {
    if (threadIdx.x < E_EXP) g_cnt[threadIdx.x] = 0;
}

__global__ void router_kernel(const float* __restrict__ x,
                              const float* __restrict__ gw,
                              const float* __restrict__ bias) {
    __shared__ float xs[D_DIM];
    __shared__ float logits[E_EXP];
    int t = blockIdx.x;
    const float4* xr = (const float4*)(x + (size_t)t * D_DIM);
    for (int i = threadIdx.x; i < D_DIM / 4; i += blockDim.x)
        ((float4*)xs)[i] = xr[i];
    __syncthreads();

    int e = threadIdx.x >> 2;
    int g = threadIdx.x & 3;
    const float4* wrow = (const float4*)(gw + (size_t)e * D_DIM);
    float s = 0.f;
    for (int d4 = g; d4 < D_DIM / 4; d4 += 4) {
        float4 a = ((const float4*)xs)[d4];
        float4 b = wrow[d4];
        s += a.x * b.x + a.y * b.y + a.z * b.z + a.w * b.w;
    }
    s += __shfl_down_sync(0xffffffffu, s, 2, 4);
    s += __shfl_down_sync(0xffffffffu, s, 1, 4);
    if (g == 0) logits[e] = s + bias[e];
    __syncthreads();

    if (threadIdx.x == 0) {
        float v[TOPK]; int idx[TOPK];
        unsigned used = 0;
        for (int k = 0; k < TOPK; k++) {
            float best = -3.4e38f; int bi = 0;
            for (int j = 0; j < E_EXP; j++) {
                if (used & (1u << j)) continue;
                if (logits[j] > best) { best = logits[j]; bi = j; }
            }
            used |= 1u << bi; v[k] = best; idx[k] = bi;
        }
        float ex[TOPK], sum = 0.f;
        for (int k = 0; k < TOPK; k++) { ex[k] = __expf(v[k] - v[0]); sum += ex[k]; }
        float inv = 1.f / sum;
        for (int k = 0; k < TOPK; k++) {
            int ek = idx[k];
            int slot = atomicAdd(&g_cnt[ek], 1);
            g_pairs[ek * T_TOK + slot] = t * TOPK + k;
            g_w[t * TOPK + k] = ex[k] * inv;
        }
    }
}

// stats + compact work-list builder
__global__ void stats_kernel(float* __restrict__ tail) {
    int e = threadIdx.x;
    float c = (float)g_cnt[e];
    float mean = (float)(T_TOK * TOPK) / E_EXP;
    float d = c - mean;
    float v = d * d;
    for (int o = 16; o > 0; o >>= 1) v += __shfl_down_sync(0xffffffffu, v, o);
    if (tail) {
        tail[e] = c;
        if (e == 0) tail[E_EXP] = sqrtf(v / E_EXP) / (mean + 1e-6f);
    }
    if (threadIdx.x == 0) {
        int n = 0;
        for (int z = 0; z < E_EXP; ++z) {
            int tiles = (g_cnt[z] + 127) >> 7;
            for (int mt = 0; mt < tiles && n < MAXW; ++mt)
                g_work[n++] = (z << 16) | mt;
        }
        for (int mt = 0; mt < T_TOK / 128 && n < MAXW; ++mt)
            g_work[n++] = (E_EXP << 16) | mt;
        g_nwork = n;
    }
}

// ================= gate+up warp-MMA (fp16 2-term, ks-staggered) =================
// CTA 128M x 64N(F), 512 threads, 16 warps: 8 gate + 8 up, each 32x32. BK=64.
#define APITCH 144
#define GU_A_HI 0
#define GU_BG_HI 18432
#define GU_BG_LO 27648
#define GU_BU_HI 36864
#define GU_BU_LO 46080
#define GU_STAGE 55296
#define GU_SMEM (1024 + 2 * GU_STAGE)   // 111616

__global__ void __launch_bounds__(512, 1)
gu_mma(const float* __restrict__ x,
       const float* __restrict__ Wg, const float* __restrict__ Wu,
       const float* __restrict__ wsg, const float* __restrict__ wsu) {
    extern __shared__ char smem[];
    int tid = threadIdx.x;
    int wi = blockIdx.y;
    if (wi >= g_nwork) return;
    int code = g_work[wi];
    int z = code >> 16;
    int mt = code & 0xffff;
    bool SH = (z == E_EXP);
    int ne = SH ? T_TOK : g_cnt[z];
    int m0 = mt * 128;
    int n0 = blockIdx.x * 64;
    const float* wgp = SH ? wsg : (Wg + (size_t)z * F_DIM * D_DIM);
    const float* wup = SH ? wsu : (Wu + (size_t)z * F_DIM * D_DIM);

    int* s_pair = (int*)smem;
    int* s_src  = (int*)(smem + 512);
    if (tid < 128) {
        int m = m0 + tid;
        int pair = SH ? m : ((m < ne) ? g_pairs[z * T_TOK + m] : g_pairs[z * T_TOK]);
        s_pair[tid] = pair;
        s_src[tid]  = SH ? m : (pair >> 2);
    }
    __syncthreads();

    const int c4 = tid & 15;       // float4 column within K-chunk
    const int rb = tid >> 4;       // base row (0..31)

    const float* aptr[4];
#pragma unroll
    for (int j = 0; j < 4; ++j)
        aptr[j] = x + (size_t)s_src[rb + 32 * j] * D_DIM + c4 * 4;
    const float* gptr[2];
    const float* uptr[2];
#pragma unroll
    for (int j = 0; j < 2; ++j) {
        gptr[j] = wgp + (size_t)(n0 + rb + 32 * j) * D_DIM + c4 * 4;
        uptr[j] = wup + (size_t)(n0 + rb + 32 * j) * D_DIM + c4 * 4;
    }

    const int wid = tid >> 5, lane = tid & 31;
    const bool isUp = wid >= 8;
    const int q = wid & 7;
    const int wm = q >> 1, wn = q & 1;   // warp: rows wm*32, cols wn*32
    const int ksrot = wid & 3;           // per-warp K-slice rotation

    float acc[2][4][4] = {};

    float4 ra[4], rg[2], ru[2];
#pragma unroll
    for (int j = 0; j < 4; ++j) ra[j] = *(const float4*)(aptr[j]);
#pragma unroll
    for (int j = 0; j < 2; ++j) { rg[j] = *(const float4*)(gptr[j]); ru[j] = *(const float4*)(uptr[j]); }

    const uint32_t a_row = wm * 32 + (lane & 15);
    const uint32_t a_colb = (lane >> 4) * 16;
    const uint32_t b_row = wn * 32 + ((lane >> 3) >> 1) * 8 + (lane & 7);
    const uint32_t b_colb = ((lane >> 3) & 1) * 16;

#define GU_STORE(BUF) do { \
    char* p; \
    _Pragma("unroll") \
    for (int j = 0; j < 4; ++j) { \
        p = (BUF) + (rb + 32 * j) * APITCH + c4 * 8; \
        h16_store4(p + GU_A_HI, ra[j]); \
    } \
    _Pragma("unroll") \
    for (int j = 0; j < 2; ++j) { \
        p = (BUF) + (rb + 32 * j) * APITCH + c4 * 8; \
        split_store4(p + GU_BG_HI, p + GU_BG_LO, rg[j]); \
        split_store4(p + GU_BU_HI, p + GU_BU_LO, ru[j]); \
    } \
} while (0)

    GU_STORE(smem + 1024);
    __syncthreads();

    for (int ch = 0; ch < 16; ++ch) {
        if (ch < 15) {
            int k0 = (ch + 1) * 64;
#pragma unroll
            for (int j = 0; j < 4; ++j) ra[j] = *(const float4*)(aptr[j] + k0);
#pragma unroll
            for (int j = 0; j < 2; ++j) { rg[j] = *(const float4*)(gptr[j] + k0); ru[j] = *(const float4*)(uptr[j] + k0); }
        }
        {
            char* cur = smem + 1024 + (ch & 1) * GU_STAGE;
            uint32_t abase = smem_u32(cur) + GU_A_HI;
            uint32_t bbase = smem_u32(cur) + (isUp ? GU_BU_HI : GU_BG_HI);
#pragma unroll
            for (int i = 0; i < 4; ++i) {
                int ks = (i + ksrot) & 3;     // staggered K-slice order per warp
                uint32_t koff = (uint32_t)ks * 32;
                uint32_t ah[2][4];
#pragma unroll
                for (int mt2 = 0; mt2 < 2; ++mt2) {
                    uint32_t ad = abase + (a_row + mt2 * 16) * APITCH + koff + a_colb;
                    ldm4(ah[mt2], ad);
                }
                uint32_t bh[8], bl[8];
#pragma unroll
                for (int p2 = 0; p2 < 2; ++p2) {
                    uint32_t bd = bbase + (b_row + p2 * 16) * APITCH + koff + b_colb;
                    ldm4(&bh[p2 * 4], bd);
                    ldm4(&bl[p2 * 4], bd + (GU_BG_LO - GU_BG_HI));
                }
                // 2-term fp16: Ah*Bh + Ah*Bl (term-major for ILP)
#pragma unroll
                for (int mt2 = 0; mt2 < 2; ++mt2)
#pragma unroll
                    for (int nt = 0; nt < 4; ++nt)
                        mma16816(acc[mt2][nt], ah[mt2], &bh[nt * 2]);
#pragma unroll
                for (int mt2 = 0; mt2 < 2; ++mt2)
#pragma unroll
                    for (int nt = 0; nt < 4; ++nt)
                        mma16816(acc[mt2][nt], ah[mt2], &bl[nt * 2]);
            }
        }
        if (ch < 15) {
            char* nxt = smem + 1024 + ((ch + 1) & 1) * GU_STAGE;
            GU_STORE(nxt);
            __syncthreads();
        }
    }
    __syncthreads();

    // epilogue: stage gate+up fp32, silu, store fp16 h
    float* stg_g = (float*)(smem + 1024);
    float* stg_u = stg_g + 128 * 66;
    float* mystg = isUp ? stg_u : stg_g;
#pragma unroll
    for (int mt2 = 0; mt2 < 2; ++mt2)
#pragma unroll
        for (int nt = 0; nt < 4; ++nt) {
            int r = wm * 32 + mt2 * 16 + (lane >> 2);
            int c = wn * 32 + nt * 8 + (lane & 3) * 2;
            *(float2*)&mystg[r * 66 + c]       = make_float2(acc[mt2][nt][0], acc[mt2][nt][1]);
            *(float2*)&mystg[(r + 8) * 66 + c] = make_float2(acc[mt2][nt][2], acc[mt2][nt][3]);
        }
    __syncthreads();

    __half* dst = SH ? g_hsp : g_hp;
    {
        int r = tid >> 2;
        int c0 = (tid & 3) * 16;
        __half* drow = dst + (size_t)s_pair[r] * F_DIM + n0 + c0;
#pragma unroll
        for (int jj = 0; jj < 16; jj += 8) {
            uint4 o;
            uint32_t* po = &o.x;
#pragma unroll
            for (int k = 0; k < 4; ++k) {
                float g0 = stg_g[r * 66 + c0 + jj + 2 * k];
                float g1 = stg_g[r * 66 + c0 + jj + 2 * k + 1];
                float u0 = stg_u[r * 66 + c0 + jj + 2 * k];
                float u1 = stg_u[r * 66 + c0 + jj + 2 * k + 1];
                float h0 = g0 / (1.f + __expf(-g0)) * u0;
                float h1 = g1 / (1.f + __expf(-g1)) * u1;
                __half2 ph = __floats2half2_rn(h0, h1);
                po[k] = h2bits(ph);
            }
            *(uint4*)(drow + jj) = o;
        }
    }
}

// ================= down warp-MMA (fp16 2-term, ks-staggered) =================
// CTA 128M x 128N(D), 512 threads, 16 warps of 32x32 (4x4). BK=64 over F.
#define DN_A 0
#define DN_B_HI 18432
#define DN_B_LO 36864
#define DN_STAGE 55296
#define DN_SMEM (1024 + 2 * DN_STAGE)   // 111616

__global__ void __launch_bounds__(512, 1)
dn_mma(const float* __restrict__ Wd, const float* __restrict__ wsd,
       float* __restrict__ out) {
    extern __shared__ char smem[];
    int tid = threadIdx.x;
    int wi = blockIdx.y;
    if (wi >= g_nwork) return;
    int code = g_work[wi];
    int z = code >> 16;
    int mt = code & 0xffff;
    bool SH = (z == E_EXP);
    int ne = SH ? T_TOK : g_cnt[z];
    int m0 = mt * 128;
    int n0 = blockIdx.x * 128;
    const float* wdp = SH ? wsd : (Wd + (size_t)z * D_DIM * F_DIM);
    const __half* hsrc = SH ? g_hsp : g_hp;

    int* s_pair = (int*)smem;
    if (tid < 128) {
        int m = m0 + tid;
        s_pair[tid] = SH ? m : ((m < ne) ? g_pairs[z * T_TOK + m] : g_pairs[z * T_TOK]);
    }
    __syncthreads();

    // A loader: fp16 source, 128 rows x 128B per chunk -> 1024 uint4, 2/thread
    const __half* haptr[2];
    unsigned soA[2];
#pragma unroll
    for (int j = 0; j < 2; ++j) {
        int idx = tid + 512 * j;
        int row = idx >> 3, c8 = idx & 7;
        haptr[j] = hsrc + (size_t)s_pair[row] * F_DIM + c8 * 8;
        soA[j]   = row * APITCH + c8 * 16;
    }
    // B loader: fp32 source, 128 rows x 16 f4 -> 4/thread
    const int c4 = tid & 15;
    const int rbB = tid >> 4;
    const float* bptr[4];
#pragma unroll
    for (int j = 0; j < 4; ++j)
        bptr[j] = wdp + (size_t)(n0 + rbB + 32 * j) * F_DIM + c4 * 4;

    const int wid = tid >> 5, lane = tid & 31;
    const int wm = wid >> 2, wn = wid & 3;   // rows wm*32, cols wn*32
    const int ksrot = wid & 3;

    float acc[2][4][4] = {};

    uint4  rha[2];
    float4 rwb[4];
#pragma unroll
    for (int j = 0; j < 2; ++j) rha[j] = *(const uint4*)(haptr[j]);
#pragma unroll
    for (int j = 0; j < 4; ++j) rwb[j] = *(const float4*)(bptr[j]);

    const uint32_t a_row = wm * 32 + (lane & 15);
    const uint32_t a_colb = (lane >> 4) * 16;
    const uint32_t b_row = wn * 32 + ((lane >> 3) >> 1) * 8 + (lane & 7);
    const uint32_t b_colb = ((lane >> 3) & 1) * 16;

#define DN_STORE(BUF) do { \
    char* b_ = (BUF); \
    _Pragma("unroll") \
    for (int j = 0; j < 2; ++j) \
        *(uint4*)(b_ + DN_A + soA[j]) = rha[j]; \
    _Pragma("unroll") \
    for (int j = 0; j < 4; ++j) { \
        char* p = b_ + (rbB + 32 * j) * APITCH + c4 * 8; \
        split_store4(p + DN_B_HI, p + DN_B_LO, rwb[j]); \
    } \
} while (0)

    DN_STORE(smem + 1024);
    __syncthreads();

    for (int ch = 0; ch < 32; ++ch) {
        if (ch < 31) {
            int k0 = (ch + 1) * 64;
#pragma unroll
            for (int j = 0; j < 2; ++j) rha[j] = *(const uint4*)(haptr[j] + k0);
#pragma unroll
            for (int j = 0; j < 4; ++j) rwb[j] = *(const float4*)(bptr[j] + k0);
        }
        {
            char* cur = smem + 1024 + (ch & 1) * DN_STAGE;
            uint32_t abase = smem_u32(cur) + DN_A;
            uint32_t bbase = smem_u32(cur) + DN_B_HI;
#pragma unroll
            for (int i = 0; i < 4; ++i) {
                int ks = (i + ksrot) & 3;
                uint32_t koff = (uint32_t)ks * 32;
                uint32_t ah[2][4];
#pragma unroll
                for (int mt2 = 0; mt2 < 2; ++mt2) {
                    uint32_t ad = abase + (a_row + mt2 * 16) * APITCH + koff + a_colb;
                    ldm4(ah[mt2], ad);
                }
                uint32_t bh[8], bl[8];
#pragma unroll
                for (int p2 = 0; p2 < 2; ++p2) {
                    uint32_t bd = bbase + (b_row + p2 * 16) * APITCH + koff + b_colb;
                    ldm4(&bh[p2 * 4], bd);
                    ldm4(&bl[p2 * 4], bd + (DN_B_LO - DN_B_HI));
                }
#pragma unroll
                for (int mt2 = 0; mt2 < 2; ++mt2)
#pragma unroll
                    for (int nt = 0; nt < 4; ++nt)
                        mma16816(acc[mt2][nt], ah[mt2], &bh[nt * 2]);
#pragma unroll
                for (int mt2 = 0; mt2 < 2; ++mt2)
#pragma unroll
                    for (int nt = 0; nt < 4; ++nt)
                        mma16816(acc[mt2][nt], ah[mt2], &bl[nt * 2]);
            }
        }
        if (ch < 31) {
            char* nxt = smem + 1024 + ((ch + 1) & 1) * DN_STAGE;
            DN_STORE(nxt);
            __syncthreads();
        }
    }
    __syncthreads();

    float* stg = (float*)(smem + 1024);
#pragma unroll
    for (int mt2 = 0; mt2 < 2; ++mt2)
#pragma unroll
        for (int nt = 0; nt < 4; ++nt) {
            int r = wm * 32 + mt2 * 16 + (lane >> 2);
            int c = wn * 32 + nt * 8 + (lane & 3) * 2;
            *(float2*)&stg[r * 132 + c]       = make_float2(acc[mt2][nt][0], acc[mt2][nt][1]);
            *(float2*)&stg[(r + 8) * 132 + c] = make_float2(acc[mt2][nt][2], acc[mt2][nt][3]);
        }
    __syncthreads();

    {
        int r = tid >> 2;
        int c0 = (tid & 3) * 32;
        float* drow;
        if (SH) drow = out + (size_t)(m0 + r) * D_DIM + n0 + c0;
        else    drow = g_y + (size_t)s_pair[r] * D_DIM + n0 + c0;
#pragma unroll
        for (int jj = 0; jj < 32; jj += 4) {
            float4 v = make_float4(stg[r * 132 + c0 + jj], stg[r * 132 + c0 + jj + 1],
                                   stg[r * 132 + c0 + jj + 2], stg[r * 132 + c0 + jj + 3]);
            *(float4*)(drow + jj) = v;
        }
    }
}

// ================= combine: out += sum_k w_k * y_pair =================
__global__ void combine_kernel(float* __restrict__ out) {
    int t = blockIdx.x;
    int c = threadIdx.x * 4;
    float4 o = *(float4*)(out + (size_t)t * D_DIM + c);
#pragma unroll
    for (int k = 0; k < TOPK; ++k) {
        int pair = t * TOPK + k;
        float w = g_w[pair];
        float4 y = *(const float4*)(g_y + (size_t)pair * D_DIM + c);
        o.x += w * y.x; o.y += w * y.y; o.z += w * y.z; o.w += w * y.w;
    }
    *(float4*)(out + (size_t)t * D_DIM + c) = o;
}

// ---------------- launch ----------------
extern "C" void kernel_launch(void* const* d_in, const int* in_sizes, int n_in,
                              void* d_out, int out_size) {
    const float* x    = (const float*)d_in[0];
    const float* gw   = (const float*)d_in[1];
    const float* bias = (const float*)d_in[2];
    const float* wg   = (const float*)d_in[3];
    const float* wu   = (const float*)d_in[4];
    const float* wd   = (const float*)d_in[5];
    const float* wsg  = (const float*)d_in[6];
    const float* wsu  = (const float*)d_in[7];
    const float* wsd  = (const float*)d_in[8];
    float* out = (float*)d_out;

    static int attr_done = 0;
    if (!attr_done) {
        cudaFuncSetAttribute(gu_mma, cudaFuncAttributeMaxDynamicSharedMemorySize, GU_SMEM);
        cudaFuncSetAttribute(dn_mma, cudaFuncAttributeMaxDynamicSharedMemorySize, DN_SMEM);
        attr_done = 1;
    }

    zero_kernel<<<1, 32>>>();
    router_kernel<<<T_TOK, 128>>>(x, gw, bias);

    float* tail = (out_size >= T_TOK * D_DIM + E_EXP + 1) ? (out + T_TOK * D_DIM) : nullptr;
    stats_kernel<<<1, 32>>>(tail);

    // gate+up: compact work list (routed + shared)
    gu_mma<<<dim3(F_DIM / 64, MAXW), 512, GU_SMEM>>>(x, wg, wu, wsg, wsu);

    // down: compact work list (routed -> g_y, shared -> out)
    dn_mma<<<dim3(D_DIM / 128, MAXW), 512, DN_SMEM>>>(wd, wsd, out);

    // weighted combine
    combine_kernel<<<T_TOK, 256>>>(out);
}

// round 13
// speedup vs baseline: 2.2837x; 1.0784x over previous
#include <cuda_runtime.h>
#include <cuda_fp16.h>
#include <stdint.h>

#define T_TOK 1024
#define D_DIM 1024
#define F_DIM 2048
#define E_EXP 32
#define TOPK  4
#define NPAIR (T_TOK * TOPK)
#define MAXW  96

// ---------------- static scratch ----------------
__device__ int     g_cnt[E_EXP];
__device__ int     g_pairs[E_EXP * T_TOK];
__device__ float   g_w[NPAIR];
__device__ __half  g_hp[(size_t)NPAIR * F_DIM];    // routed hidden fp16
__device__ __half  g_hsp[(size_t)T_TOK * F_DIM];   // shared hidden fp16
__device__ float   g_y[(size_t)NPAIR * D_DIM];     // routed per-pair down output
__device__ int     g_nwork;
__device__ int     g_work[MAXW];                   // (z<<16)|mt ; z==E_EXP -> shared

// ---------------- helpers ----------------
__device__ __forceinline__ uint32_t smem_u32(const void* p) {
    uint32_t a;
    asm("{ .reg .u64 t; cvta.to.shared.u64 t, %1; cvt.u32.u64 %0, t; }" : "=r"(a) : "l"(p));
    return a;
}
__device__ __forceinline__ void ldm4(uint32_t* r, uint32_t addr) {
    asm volatile("ldmatrix.sync.aligned.m8n8.x4.shared.b16 {%0,%1,%2,%3}, [%4];"
                 : "=r"(r[0]), "=r"(r[1]), "=r"(r[2]), "=r"(r[3]) : "r"(addr));
}
__device__ __forceinline__ void mma16816(float* d, const uint32_t* a, const uint32_t* b) {
    asm volatile("mma.sync.aligned.m16n8k16.row.col.f32.f16.f16.f32 "
                 "{%0,%1,%2,%3}, {%4,%5,%6,%7}, {%8,%9}, {%0,%1,%2,%3};"
                 : "+f"(d[0]), "+f"(d[1]), "+f"(d[2]), "+f"(d[3])
                 : "r"(a[0]), "r"(a[1]), "r"(a[2]), "r"(a[3]), "r"(b[0]), "r"(b[1]));
}
__device__ __forceinline__ uint32_t h2bits(__half2 h) {
    return *reinterpret_cast<uint32_t*>(&h);
}
// fp16 split of two floats: hi = rn(x), lo = rn(x - hi)
__device__ __forceinline__ void cvt_split16(float x0, float x1, uint32_t& hi, uint32_t& lo) {
    __half2 h = __floats2half2_rn(x0, x1);
    hi = h2bits(h);
    float f0 = __half2float(__low2half(h));
    float f1 = __half2float(__high2half(h));
    __half2 l = __floats2half2_rn(x0 - f0, x1 - f1);
    lo = h2bits(l);
}
__device__ __forceinline__ void split_store4(char* hi, char* lo, float4 v) {
    uint32_t h0, l0, h1, l1;
    cvt_split16(v.x, v.y, h0, l0);
    cvt_split16(v.z, v.w, h1, l1);
    *(uint2*)hi = make_uint2(h0, h1);
    *(uint2*)lo = make_uint2(l0, l1);
}
__device__ __forceinline__ void h16_store4(char* dst, float4 v) {
    __half2 a = __floats2half2_rn(v.x, v.y);
    __half2 b = __floats2half2_rn(v.z, v.w);
    *(uint2*)dst = make_uint2(h2bits(a), h2bits(b));
}

// ---------------- tiny kernels ----------------
__global__ void zero_kernel() {
    if (threadIdx.x < E_EXP) g_cnt[threadIdx.x] = 0;
}

__global__ void router_kernel(const float* __restrict__ x,
                              const float* __restrict__ gw,
                              const float* __restrict__ bias) {
    __shared__ float xs[D_DIM];
    __shared__ float logits[E_EXP];
    int t = blockIdx.x;
    const float4* xr = (const float4*)(x + (size_t)t * D_DIM);
    for (int i = threadIdx.x; i < D_DIM / 4; i += blockDim.x)
        ((float4*)xs)[i] = xr[i];
    __syncthreads();

    int e = threadIdx.x >> 2;
    int g = threadIdx.x & 3;
    const float4* wrow = (const float4*)(gw + (size_t)e * D_DIM);
    float s = 0.f;
    for (int d4 = g; d4 < D_DIM / 4; d4 += 4) {
        float4 a = ((const float4*)xs)[d4];
        float4 b = wrow[d4];
        s += a.x * b.x + a.y * b.y + a.z * b.z + a.w * b.w;
    }
    s += __shfl_down_sync(0xffffffffu, s, 2, 4);
    s += __shfl_down_sync(0xffffffffu, s, 1, 4);
    if (g == 0) logits[e] = s + bias[e];
    __syncthreads();

    if (threadIdx.x == 0) {
        float v[TOPK]; int idx[TOPK];
        unsigned used = 0;
        for (int k = 0; k < TOPK; k++) {
            float best = -3.4e38f; int bi = 0;
            for (int j = 0; j < E_EXP; j++) {
                if (used & (1u << j)) continue;
                if (logits[j] > best) { best = logits[j]; bi = j; }
            }
            used |= 1u << bi; v[k] = best; idx[k] = bi;
        }
        float ex[TOPK], sum = 0.f;
        for (int k = 0; k < TOPK; k++) { ex[k] = __expf(v[k] - v[0]); sum += ex[k]; }
        float inv = 1.f / sum;
        for (int k = 0; k < TOPK; k++) {
            int ek = idx[k];
            int slot = atomicAdd(&g_cnt[ek], 1);
            g_pairs[ek * T_TOK + slot] = t * TOPK + k;
            g_w[t * TOPK + k] = ex[k] * inv;
        }
    }
}

// stats + compact work-list builder
__global__ void stats_kernel(float* __restrict__ tail) {
    int e = threadIdx.x;
    float c = (float)g_cnt[e];
    float mean = (float)(T_TOK * TOPK) / E_EXP;
    float d = c - mean;
    float v = d * d;
    for (int o = 16; o > 0; o >>= 1) v += __shfl_down_sync(0xffffffffu, v, o);
    if (tail) {
        tail[e] = c;
        if (e == 0) tail[E_EXP] = sqrtf(v / E_EXP) / (mean + 1e-6f);
    }
    if (threadIdx.x == 0) {
        int n = 0;
        for (int z = 0; z < E_EXP; ++z) {
            int tiles = (g_cnt[z] + 127) >> 7;
            for (int mt = 0; mt < tiles && n < MAXW; ++mt)
                g_work[n++] = (z << 16) | mt;
        }
        for (int mt = 0; mt < T_TOK / 128 && n < MAXW; ++mt)
            g_work[n++] = (E_EXP << 16) | mt;
        g_nwork = n;
    }
}

// ================= gate+up warp-MMA (fp16 2-term, ks-staggered) — unchanged R12 =================
// CTA 128M x 64N(F), 512 threads, 16 warps: 8 gate + 8 up, each 32x32. BK=64.
#define APITCH 144
#define GU_A_HI 0
#define GU_BG_HI 18432
#define GU_BG_LO 27648
#define GU_BU_HI 36864
#define GU_BU_LO 46080
#define GU_STAGE 55296
#define GU_SMEM (1024 + 2 * GU_STAGE)   // 111616

__global__ void __launch_bounds__(512, 1)
gu_mma(const float* __restrict__ x,
       const float* __restrict__ Wg, const float* __restrict__ Wu,
       const float* __restrict__ wsg, const float* __restrict__ wsu) {
    extern __shared__ char smem[];
    int tid = threadIdx.x;
    int wi = blockIdx.y;
    if (wi >= g_nwork) return;
    int code = g_work[wi];
    int z = code >> 16;
    int mt = code & 0xffff;
    bool SH = (z == E_EXP);
    int ne = SH ? T_TOK : g_cnt[z];
    int m0 = mt * 128;
    int n0 = blockIdx.x * 64;
    const float* wgp = SH ? wsg : (Wg + (size_t)z * F_DIM * D_DIM);
    const float* wup = SH ? wsu : (Wu + (size_t)z * F_DIM * D_DIM);

    int* s_pair = (int*)smem;
    int* s_src  = (int*)(smem + 512);
    if (tid < 128) {
        int m = m0 + tid;
        int pair = SH ? m : ((m < ne) ? g_pairs[z * T_TOK + m] : g_pairs[z * T_TOK]);
        s_pair[tid] = pair;
        s_src[tid]  = SH ? m : (pair >> 2);
    }
    __syncthreads();

    const int c4 = tid & 15;
    const int rb = tid >> 4;

    const float* aptr[4];
#pragma unroll
    for (int j = 0; j < 4; ++j)
        aptr[j] = x + (size_t)s_src[rb + 32 * j] * D_DIM + c4 * 4;
    const float* gptr[2];
    const float* uptr[2];
#pragma unroll
    for (int j = 0; j < 2; ++j) {
        gptr[j] = wgp + (size_t)(n0 + rb + 32 * j) * D_DIM + c4 * 4;
        uptr[j] = wup + (size_t)(n0 + rb + 32 * j) * D_DIM + c4 * 4;
    }

    const int wid = tid >> 5, lane = tid & 31;
    const bool isUp = wid >= 8;
    const int q = wid & 7;
    const int wm = q >> 1, wn = q & 1;
    const int ksrot = wid & 3;

    float acc[2][4][4] = {};

    float4 ra[4], rg[2], ru[2];
#pragma unroll
    for (int j = 0; j < 4; ++j) ra[j] = *(const float4*)(aptr[j]);
#pragma unroll
    for (int j = 0; j < 2; ++j) { rg[j] = *(const float4*)(gptr[j]); ru[j] = *(const float4*)(uptr[j]); }

    const uint32_t a_row = wm * 32 + (lane & 15);
    const uint32_t a_colb = (lane >> 4) * 16;
    const uint32_t b_row = wn * 32 + ((lane >> 3) >> 1) * 8 + (lane & 7);
    const uint32_t b_colb = ((lane >> 3) & 1) * 16;

#define GU_STORE(BUF) do { \
    char* p; \
    _Pragma("unroll") \
    for (int j = 0; j < 4; ++j) { \
        p = (BUF) + (rb + 32 * j) * APITCH + c4 * 8; \
        h16_store4(p + GU_A_HI, ra[j]); \
    } \
    _Pragma("unroll") \
    for (int j = 0; j < 2; ++j) { \
        p = (BUF) + (rb + 32 * j) * APITCH + c4 * 8; \
        split_store4(p + GU_BG_HI, p + GU_BG_LO, rg[j]); \
        split_store4(p + GU_BU_HI, p + GU_BU_LO, ru[j]); \
    } \
} while (0)

    GU_STORE(smem + 1024);
    __syncthreads();

    for (int ch = 0; ch < 16; ++ch) {
        if (ch < 15) {
            int k0 = (ch + 1) * 64;
#pragma unroll
            for (int j = 0; j < 4; ++j) ra[j] = *(const float4*)(aptr[j] + k0);
#pragma unroll
            for (int j = 0; j < 2; ++j) { rg[j] = *(const float4*)(gptr[j] + k0); ru[j] = *(const float4*)(uptr[j] + k0); }
        }
        {
            char* cur = smem + 1024 + (ch & 1) * GU_STAGE;
            uint32_t abase = smem_u32(cur) + GU_A_HI;
            uint32_t bbase = smem_u32(cur) + (isUp ? GU_BU_HI : GU_BG_HI);
#pragma unroll
            for (int i = 0; i < 4; ++i) {
                int ks = (i + ksrot) & 3;
                uint32_t koff = (uint32_t)ks * 32;
                uint32_t ah[2][4];
#pragma unroll
                for (int mt2 = 0; mt2 < 2; ++mt2) {
                    uint32_t ad = abase + (a_row + mt2 * 16) * APITCH + koff + a_colb;
                    ldm4(ah[mt2], ad);
                }
                uint32_t bh[8], bl[8];
#pragma unroll
                for (int p2 = 0; p2 < 2; ++p2) {
                    uint32_t bd = bbase + (b_row + p2 * 16) * APITCH + koff + b_colb;
                    ldm4(&bh[p2 * 4], bd);
                    ldm4(&bl[p2 * 4], bd + (GU_BG_LO - GU_BG_HI));
                }
#pragma unroll
                for (int mt2 = 0; mt2 < 2; ++mt2)
#pragma unroll
                    for (int nt = 0; nt < 4; ++nt)
                        mma16816(acc[mt2][nt], ah[mt2], &bh[nt * 2]);
#pragma unroll
                for (int mt2 = 0; mt2 < 2; ++mt2)
#pragma unroll
                    for (int nt = 0; nt < 4; ++nt)
                        mma16816(acc[mt2][nt], ah[mt2], &bl[nt * 2]);
            }
        }
        if (ch < 15) {
            char* nxt = smem + 1024 + ((ch + 1) & 1) * GU_STAGE;
            GU_STORE(nxt);
            __syncthreads();
        }
    }
    __syncthreads();

    // epilogue: stage gate+up fp32, silu, store fp16 h
    float* stg_g = (float*)(smem + 1024);
    float* stg_u = stg_g + 128 * 66;
    float* mystg = isUp ? stg_u : stg_g;
#pragma unroll
    for (int mt2 = 0; mt2 < 2; ++mt2)
#pragma unroll
        for (int nt = 0; nt < 4; ++nt) {
            int r = wm * 32 + mt2 * 16 + (lane >> 2);
            int c = wn * 32 + nt * 8 + (lane & 3) * 2;
            *(float2*)&mystg[r * 66 + c]       = make_float2(acc[mt2][nt][0], acc[mt2][nt][1]);
            *(float2*)&mystg[(r + 8) * 66 + c] = make_float2(acc[mt2][nt][2], acc[mt2][nt][3]);
        }
    __syncthreads();

    __half* dst = SH ? g_hsp : g_hp;
    {
        int r = tid >> 2;
        int c0 = (tid & 3) * 16;
        __half* drow = dst + (size_t)s_pair[r] * F_DIM + n0 + c0;
#pragma unroll
        for (int jj = 0; jj < 16; jj += 8) {
            uint4 o;
            uint32_t* po = &o.x;
#pragma unroll
            for (int k = 0; k < 4; ++k) {
                float g0 = stg_g[r * 66 + c0 + jj + 2 * k];
                float g1 = stg_g[r * 66 + c0 + jj + 2 * k + 1];
                float u0 = stg_u[r * 66 + c0 + jj + 2 * k];
                float u1 = stg_u[r * 66 + c0 + jj + 2 * k + 1];
                float h0 = g0 / (1.f + __expf(-g0)) * u0;
                float h1 = g1 / (1.f + __expf(-g1)) * u1;
                __half2 ph = __floats2half2_rn(h0, h1);
                po[k] = h2bits(ph);
            }
            *(uint4*)(drow + jj) = o;
        }
    }
}

// ================= down warp-MMA (fp16 SINGLE-term, ks-staggered) =================
// CTA 128M x 128N(D), 512 threads, 16 warps of 32x32 (4x4). BK=64 over F.
// A = hidden fp16 (exact); B = down-weight fp16 hi only (lo term dropped).
#define DN_A 0
#define DN_B_HI 18432
#define DN_STAGE 36864
#define DN_SMEM (1024 + 2 * DN_STAGE)   // 74752

__global__ void __launch_bounds__(512, 1)
dn_mma(const float* __restrict__ Wd, const float* __restrict__ wsd,
       float* __restrict__ out) {
    extern __shared__ char smem[];
    int tid = threadIdx.x;
    int wi = blockIdx.y;
    if (wi >= g_nwork) return;
    int code = g_work[wi];
    int z = code >> 16;
    int mt = code & 0xffff;
    bool SH = (z == E_EXP);
    int ne = SH ? T_TOK : g_cnt[z];
    int m0 = mt * 128;
    int n0 = blockIdx.x * 128;
    const float* wdp = SH ? wsd : (Wd + (size_t)z * D_DIM * F_DIM);
    const __half* hsrc = SH ? g_hsp : g_hp;

    int* s_pair = (int*)smem;
    if (tid < 128) {
        int m = m0 + tid;
        s_pair[tid] = SH ? m : ((m < ne) ? g_pairs[z * T_TOK + m] : g_pairs[z * T_TOK]);
    }
    __syncthreads();

    // A loader: fp16 source, 128 rows x 128B per chunk -> 1024 uint4, 2/thread
    const __half* haptr[2];
    unsigned soA[2];
#pragma unroll
    for (int j = 0; j < 2; ++j) {
        int idx = tid + 512 * j;
        int row = idx >> 3, c8 = idx & 7;
        haptr[j] = hsrc + (size_t)s_pair[row] * F_DIM + c8 * 8;
        soA[j]   = row * APITCH + c8 * 16;
    }
    // B loader: fp32 source, 128 rows x 16 f4 -> 4/thread (hi only)
    const int c4 = tid & 15;
    const int rbB = tid >> 4;
    const float* bptr[4];
#pragma unroll
    for (int j = 0; j < 4; ++j)
        bptr[j] = wdp + (size_t)(n0 + rbB + 32 * j) * F_DIM + c4 * 4;

    const int wid = tid >> 5, lane = tid & 31;
    const int wm = wid >> 2, wn = wid & 3;
    const int ksrot = wid & 3;

    float acc[2][4][4] = {};

    uint4  rha[2];
    float4 rwb[4];
#pragma unroll
    for (int j = 0; j < 2; ++j) rha[j] = *(const uint4*)(haptr[j]);
#pragma unroll
    for (int j = 0; j < 4; ++j) rwb[j] = *(const float4*)(bptr[j]);

    const uint32_t a_row = wm * 32 + (lane & 15);
    const uint32_t a_colb = (lane >> 4) * 16;
    const uint32_t b_row = wn * 32 + ((lane >> 3) >> 1) * 8 + (lane & 7);
    const uint32_t b_colb = ((lane >> 3) & 1) * 16;

#define DN_STORE(BUF) do { \
    char* b_ = (BUF); \
    _Pragma("unroll") \
    for (int j = 0; j < 2; ++j) \
        *(uint4*)(b_ + DN_A + soA[j]) = rha[j]; \
    _Pragma("unroll") \
    for (int j = 0; j < 4; ++j) { \
        char* p = b_ + (rbB + 32 * j) * APITCH + c4 * 8; \
        h16_store4(p + DN_B_HI, rwb[j]); \
    } \
} while (0)

    DN_STORE(smem + 1024);
    __syncthreads();

    for (int ch = 0; ch < 32; ++ch) {
        if (ch < 31) {
            int k0 = (ch + 1) * 64;
#pragma unroll
            for (int j = 0; j < 2; ++j) rha[j] = *(const uint4*)(haptr[j] + k0);
#pragma unroll
            for (int j = 0; j < 4; ++j) rwb[j] = *(const float4*)(bptr[j] + k0);
        }
        {
            char* cur = smem + 1024 + (ch & 1) * DN_STAGE;
            uint32_t abase = smem_u32(cur) + DN_A;
            uint32_t bbase = smem_u32(cur) + DN_B_HI;
#pragma unroll
            for (int i = 0; i < 4; ++i) {
                int ks = (i + ksrot) & 3;
                uint32_t koff = (uint32_t)ks * 32;
                uint32_t ah[2][4];
#pragma unroll
                for (int mt2 = 0; mt2 < 2; ++mt2) {
                    uint32_t ad = abase + (a_row + mt2 * 16) * APITCH + koff + a_colb;
                    ldm4(ah[mt2], ad);
                }
                uint32_t bh[8];
#pragma unroll
                for (int p2 = 0; p2 < 2; ++p2) {
                    uint32_t bd = bbase + (b_row + p2 * 16) * APITCH + koff + b_colb;
                    ldm4(&bh[p2 * 4], bd);
                }
#pragma unroll
                for (int mt2 = 0; mt2 < 2; ++mt2)
#pragma unroll
                    for (int nt = 0; nt < 4; ++nt)
                        mma16816(acc[mt2][nt], ah[mt2], &bh[nt * 2]);
            }
        }
        if (ch < 31) {
            char* nxt = smem + 1024 + ((ch + 1) & 1) * DN_STAGE;
            DN_STORE(nxt);
            __syncthreads();
        }
    }
    __syncthreads();

    float* stg = (float*)(smem + 1024);
#pragma unroll
    for (int mt2 = 0; mt2 < 2; ++mt2)
#pragma unroll
        for (int nt = 0; nt < 4; ++nt) {
            int r = wm * 32 + mt2 * 16 + (lane >> 2);
            int c = wn * 32 + nt * 8 + (lane & 3) * 2;
            *(float2*)&stg[r * 132 + c]       = make_float2(acc[mt2][nt][0], acc[mt2][nt][1]);
            *(float2*)&stg[(r + 8) * 132 + c] = make_float2(acc[mt2][nt][2], acc[mt2][nt][3]);
        }
    __syncthreads();

    {
        int r = tid >> 2;
        int c0 = (tid & 3) * 32;
        float* drow;
        if (SH) drow = out + (size_t)(m0 + r) * D_DIM + n0 + c0;
        else    drow = g_y + (size_t)s_pair[r] * D_DIM + n0 + c0;
#pragma unroll
        for (int jj = 0; jj < 32; jj += 4) {
            float4 v = make_float4(stg[r * 132 + c0 + jj], stg[r * 132 + c0 + jj + 1],
                                   stg[r * 132 + c0 + jj + 2], stg[r * 132 + c0 + jj + 3]);
            *(float4*)(drow + jj) = v;
        }
    }
}

// ================= combine: out += sum_k w_k * y_pair =================
__global__ void combine_kernel(float* __restrict__ out) {
    int t = blockIdx.x;
    int c = threadIdx.x * 4;
    float4 o = *(float4*)(out + (size_t)t * D_DIM + c);
#pragma unroll
    for (int k = 0; k < TOPK; ++k) {
        int pair = t * TOPK + k;
        float w = g_w[pair];
        float4 y = *(const float4*)(g_y + (size_t)pair * D_DIM + c);
        o.x += w * y.x; o.y += w * y.y; o.z += w * y.z; o.w += w * y.w;
    }
    *(float4*)(out + (size_t)t * D_DIM + c) = o;
}

// ---------------- launch ----------------
extern "C" void kernel_launch(void* const* d_in, const int* in_sizes, int n_in,
                              void* d_out, int out_size) {
    const float* x    = (const float*)d_in[0];
    const float* gw   = (const float*)d_in[1];
    const float* bias = (const float*)d_in[2];
    const float* wg   = (const float*)d_in[3];
    const float* wu   = (const float*)d_in[4];
    const float* wd   = (const float*)d_in[5];
    const float* wsg  = (const float*)d_in[6];
    const float* wsu  = (const float*)d_in[7];
    const float* wsd  = (const float*)d_in[8];
    float* out = (float*)d_out;

    static int attr_done = 0;
    if (!attr_done) {
        cudaFuncSetAttribute(gu_mma, cudaFuncAttributeMaxDynamicSharedMemorySize, GU_SMEM);
        cudaFuncSetAttribute(dn_mma, cudaFuncAttributeMaxDynamicSharedMemorySize, DN_SMEM);
        attr_done = 1;
    }

    zero_kernel<<<1, 32>>>();
    router_kernel<<<T_TOK, 128>>>(x, gw, bias);

    float* tail = (out_size >= T_TOK * D_DIM + E_EXP + 1) ? (out + T_TOK * D_DIM) : nullptr;
    stats_kernel<<<1, 32>>>(tail);

    // gate+up: compact work list (routed + shared)
    gu_mma<<<dim3(F_DIM / 64, MAXW), 512, GU_SMEM>>>(x, wg, wu, wsg, wsu);

    // down: compact work list (routed -> g_y, shared -> out)
    dn_mma<<<dim3(D_DIM / 128, MAXW), 512, DN_SMEM>>>(wd, wsd, out);

    // weighted combine
    combine_kernel<<<T_TOK, 256>>>(out);
}

// round 14
// speedup vs baseline: 2.8391x; 1.2432x over previous
#include <cuda_runtime.h>
#include <cuda_fp16.h>
#include <stdint.h>

#define T_TOK 1024
#define D_DIM 1024
#define F_DIM 2048
#define E_EXP 32
#define TOPK  4
#define NPAIR (T_TOK * TOPK)
#define MAXW  96

// ---------------- static scratch ----------------
__device__ int     g_cnt[E_EXP];
__device__ int     g_pairs[E_EXP * T_TOK];
__device__ float   g_w[NPAIR];
__device__ __half  g_hp[(size_t)NPAIR * F_DIM];    // routed hidden fp16
__device__ __half  g_hsp[(size_t)T_TOK * F_DIM];   // shared hidden fp16
__device__ float   g_y[(size_t)NPAIR * D_DIM];     // routed per-pair down output
__device__ int     g_nwork;
__device__ int     g_work[MAXW];                   // (z<<16)|mt ; z==E_EXP -> shared

// ---------------- helpers ----------------
__device__ __forceinline__ uint32_t smem_u32(const void* p) {
    uint32_t a;
    asm("{ .reg .u64 t; cvta.to.shared.u64 t, %1; cvt.u32.u64 %0, t; }" : "=r"(a) : "l"(p));
    return a;
}
__device__ __forceinline__ void ldm4(uint32_t* r, uint32_t addr) {
    asm volatile("ldmatrix.sync.aligned.m8n8.x4.shared.b16 {%0,%1,%2,%3}, [%4];"
                 : "=r"(r[0]), "=r"(r[1]), "=r"(r[2]), "=r"(r[3]) : "r"(addr));
}
__device__ __forceinline__ void mma16816(float* d, const uint32_t* a, const uint32_t* b) {
    asm volatile("mma.sync.aligned.m16n8k16.row.col.f32.f16.f16.f32 "
                 "{%0,%1,%2,%3}, {%4,%5,%6,%7}, {%8,%9}, {%0,%1,%2,%3};"
                 : "+f"(d[0]), "+f"(d[1]), "+f"(d[2]), "+f"(d[3])
                 : "r"(a[0]), "r"(a[1]), "r"(a[2]), "r"(a[3]), "r"(b[0]), "r"(b[1]));
}
__device__ __forceinline__ uint32_t h2bits(__half2 h) {
    return *reinterpret_cast<uint32_t*>(&h);
}
__device__ __forceinline__ void h16_store4(char* dst, float4 v) {
    __half2 a = __floats2half2_rn(v.x, v.y);
    __half2 b = __floats2half2_rn(v.z, v.w);
    *(uint2*)dst = make_uint2(h2bits(a), h2bits(b));
}

// ---------------- tiny kernels ----------------
__global__ void zero_kernel() {
    if (threadIdx.x < E_EXP) g_cnt[threadIdx.x] = 0;
}

__global__ void router_kernel(const float* __restrict__ x,
                              const float* __restrict__ gw,
                              const float* __restrict__ bias) {
    __shared__ float xs[D_DIM];
    __shared__ float logits[E_EXP];
    int t = blockIdx.x;
    const float4* xr = (const float4*)(x + (size_t)t * D_DIM);
    for (int i = threadIdx.x; i < D_DIM / 4; i += blockDim.x)
        ((float4*)xs)[i] = xr[i];
    __syncthreads();

    int e = threadIdx.x >> 2;
    int g = threadIdx.x & 3;
    const float4* wrow = (const float4*)(gw + (size_t)e * D_DIM);
    float s = 0.f;
    for (int d4 = g; d4 < D_DIM / 4; d4 += 4) {
        float4 a = ((const float4*)xs)[d4];
        float4 b = wrow[d4];
        s += a.x * b.x + a.y * b.y + a.z * b.z + a.w * b.w;
    }
    s += __shfl_down_sync(0xffffffffu, s, 2, 4);
    s += __shfl_down_sync(0xffffffffu, s, 1, 4);
    if (g == 0) logits[e] = s + bias[e];
    __syncthreads();

    if (threadIdx.x == 0) {
        float v[TOPK]; int idx[TOPK];
        unsigned used = 0;
        for (int k = 0; k < TOPK; k++) {
            float best = -3.4e38f; int bi = 0;
            for (int j = 0; j < E_EXP; j++) {
                if (used & (1u << j)) continue;
                if (logits[j] > best) { best = logits[j]; bi = j; }
            }
            used |= 1u << bi; v[k] = best; idx[k] = bi;
        }
        float ex[TOPK], sum = 0.f;
        for (int k = 0; k < TOPK; k++) { ex[k] = __expf(v[k] - v[0]); sum += ex[k]; }
        float inv = 1.f / sum;
        for (int k = 0; k < TOPK; k++) {
            int ek = idx[k];
            int slot = atomicAdd(&g_cnt[ek], 1);
            g_pairs[ek * T_TOK + slot] = t * TOPK + k;
            g_w[t * TOPK + k] = ex[k] * inv;
        }
    }
}

// stats + compact work-list builder
__global__ void stats_kernel(float* __restrict__ tail) {
    int e = threadIdx.x;
    float c = (float)g_cnt[e];
    float mean = (float)(T_TOK * TOPK) / E_EXP;
    float d = c - mean;
    float v = d * d;
    for (int o = 16; o > 0; o >>= 1) v += __shfl_down_sync(0xffffffffu, v, o);
    if (tail) {
        tail[e] = c;
        if (e == 0) tail[E_EXP] = sqrtf(v / E_EXP) / (mean + 1e-6f);
    }
    if (threadIdx.x == 0) {
        int n = 0;
        for (int z = 0; z < E_EXP; ++z) {
            int tiles = (g_cnt[z] + 127) >> 7;
            for (int mt = 0; mt < tiles && n < MAXW; ++mt)
                g_work[n++] = (z << 16) | mt;
        }
        for (int mt = 0; mt < T_TOK / 128 && n < MAXW; ++mt)
            g_work[n++] = (E_EXP << 16) | mt;
        g_nwork = n;
    }
}

// ================= gate+up warp-MMA (fp16 SINGLE-term, ks-staggered) =================
// CTA 128M x 64N(F), 512 threads, 16 warps: 8 gate + 8 up, each 32x32. BK=64.
#define APITCH 144
#define GU_A   0
#define GU_BG  18432
#define GU_BU  27648
#define GU_STAGE 36864
#define GU_SMEM (1024 + 2 * GU_STAGE)   // 74752

__global__ void __launch_bounds__(512, 1)
gu_mma(const float* __restrict__ x,
       const float* __restrict__ Wg, const float* __restrict__ Wu,
       const float* __restrict__ wsg, const float* __restrict__ wsu) {
    extern __shared__ char smem[];
    int tid = threadIdx.x;
    int wi = blockIdx.y;
    if (wi >= g_nwork) return;
    int code = g_work[wi];
    int z = code >> 16;
    int mt = code & 0xffff;
    bool SH = (z == E_EXP);
    int ne = SH ? T_TOK : g_cnt[z];
    int m0 = mt * 128;
    int n0 = blockIdx.x * 64;
    const float* wgp = SH ? wsg : (Wg + (size_t)z * F_DIM * D_DIM);
    const float* wup = SH ? wsu : (Wu + (size_t)z * F_DIM * D_DIM);

    int* s_pair = (int*)smem;
    int* s_src  = (int*)(smem + 512);
    if (tid < 128) {
        int m = m0 + tid;
        int pair = SH ? m : ((m < ne) ? g_pairs[z * T_TOK + m] : g_pairs[z * T_TOK]);
        s_pair[tid] = pair;
        s_src[tid]  = SH ? m : (pair >> 2);
    }
    __syncthreads();

    const int c4 = tid & 15;       // float4 column within K-chunk
    const int rb = tid >> 4;       // base row (0..31)

    const float* aptr[4];
#pragma unroll
    for (int j = 0; j < 4; ++j)
        aptr[j] = x + (size_t)s_src[rb + 32 * j] * D_DIM + c4 * 4;
    const float* gptr[2];
    const float* uptr[2];
#pragma unroll
    for (int j = 0; j < 2; ++j) {
        gptr[j] = wgp + (size_t)(n0 + rb + 32 * j) * D_DIM + c4 * 4;
        uptr[j] = wup + (size_t)(n0 + rb + 32 * j) * D_DIM + c4 * 4;
    }

    const int wid = tid >> 5, lane = tid & 31;
    const bool isUp = wid >= 8;
    const int q = wid & 7;
    const int wm = q >> 1, wn = q & 1;
    const int ksrot = wid & 3;

    float acc[2][4][4] = {};

    float4 ra[4], rg[2], ru[2];
#pragma unroll
    for (int j = 0; j < 4; ++j) ra[j] = *(const float4*)(aptr[j]);
#pragma unroll
    for (int j = 0; j < 2; ++j) { rg[j] = *(const float4*)(gptr[j]); ru[j] = *(const float4*)(uptr[j]); }

    const uint32_t a_row = wm * 32 + (lane & 15);
    const uint32_t a_colb = (lane >> 4) * 16;
    const uint32_t b_row = wn * 32 + ((lane >> 3) >> 1) * 8 + (lane & 7);
    const uint32_t b_colb = ((lane >> 3) & 1) * 16;

#define GU_STORE(BUF) do { \
    char* p; \
    _Pragma("unroll") \
    for (int j = 0; j < 4; ++j) { \
        p = (BUF) + (rb + 32 * j) * APITCH + c4 * 8; \
        h16_store4(p + GU_A, ra[j]); \
    } \
    _Pragma("unroll") \
    for (int j = 0; j < 2; ++j) { \
        p = (BUF) + (rb + 32 * j) * APITCH + c4 * 8; \
        h16_store4(p + GU_BG, rg[j]); \
        h16_store4(p + GU_BU, ru[j]); \
    } \
} while (0)

    GU_STORE(smem + 1024);
    __syncthreads();

    for (int ch = 0; ch < 16; ++ch) {
        if (ch < 15) {
            int k0 = (ch + 1) * 64;
#pragma unroll
            for (int j = 0; j < 4; ++j) ra[j] = *(const float4*)(aptr[j] + k0);
#pragma unroll
            for (int j = 0; j < 2; ++j) { rg[j] = *(const float4*)(gptr[j] + k0); ru[j] = *(const float4*)(uptr[j] + k0); }
        }
        {
            char* cur = smem + 1024 + (ch & 1) * GU_STAGE;
            uint32_t abase = smem_u32(cur) + GU_A;
            uint32_t bbase = smem_u32(cur) + (isUp ? GU_BU : GU_BG);
#pragma unroll
            for (int i = 0; i < 4; ++i) {
                int ks = (i + ksrot) & 3;     // staggered K-slice order per warp
                uint32_t koff = (uint32_t)ks * 32;
                uint32_t ah[2][4];
#pragma unroll
                for (int mt2 = 0; mt2 < 2; ++mt2) {
                    uint32_t ad = abase + (a_row + mt2 * 16) * APITCH + koff + a_colb;
                    ldm4(ah[mt2], ad);
                }
                uint32_t bh[8];
#pragma unroll
                for (int p2 = 0; p2 < 2; ++p2) {
                    uint32_t bd = bbase + (b_row + p2 * 16) * APITCH + koff + b_colb;
                    ldm4(&bh[p2 * 4], bd);
                }
#pragma unroll
                for (int mt2 = 0; mt2 < 2; ++mt2)
#pragma unroll
                    for (int nt = 0; nt < 4; ++nt)
                        mma16816(acc[mt2][nt], ah[mt2], &bh[nt * 2]);
            }
        }
        if (ch < 15) {
            char* nxt = smem + 1024 + ((ch + 1) & 1) * GU_STAGE;
            GU_STORE(nxt);
            __syncthreads();
        }
    }
    __syncthreads();

    // epilogue: stage gate+up fp32, silu, store fp16 h
    float* stg_g = (float*)(smem + 1024);
    float* stg_u = stg_g + 128 * 66;
    float* mystg = isUp ? stg_u : stg_g;
#pragma unroll
    for (int mt2 = 0; mt2 < 2; ++mt2)
#pragma unroll
        for (int nt = 0; nt < 4; ++nt) {
            int r = wm * 32 + mt2 * 16 + (lane >> 2);
            int c = wn * 32 + nt * 8 + (lane & 3) * 2;
            *(float2*)&mystg[r * 66 + c]       = make_float2(acc[mt2][nt][0], acc[mt2][nt][1]);
            *(float2*)&mystg[(r + 8) * 66 + c] = make_float2(acc[mt2][nt][2], acc[mt2][nt][3]);
        }
    __syncthreads();

    __half* dst = SH ? g_hsp : g_hp;
    {
        int r = tid >> 2;
        int c0 = (tid & 3) * 16;
        __half* drow = dst + (size_t)s_pair[r] * F_DIM + n0 + c0;
#pragma unroll
        for (int jj = 0; jj < 16; jj += 8) {
            uint4 o;
            uint32_t* po = &o.x;
#pragma unroll
            for (int k = 0; k < 4; ++k) {
                float g0 = stg_g[r * 66 + c0 + jj + 2 * k];
                float g1 = stg_g[r * 66 + c0 + jj + 2 * k + 1];
                float u0 = stg_u[r * 66 + c0 + jj + 2 * k];
                float u1 = stg_u[r * 66 + c0 + jj + 2 * k + 1];
                float h0 = g0 / (1.f + __expf(-g0)) * u0;
                float h1 = g1 / (1.f + __expf(-g1)) * u1;
                __half2 ph = __floats2half2_rn(h0, h1);
                po[k] = h2bits(ph);
            }
            *(uint4*)(drow + jj) = o;
        }
    }
}

// ================= down warp-MMA (fp16 single-term, ks-staggered) — unchanged R13 =================
// CTA 128M x 128N(D), 512 threads, 16 warps of 32x32 (4x4). BK=64 over F.
#define DN_A 0
#define DN_B_HI 18432
#define DN_STAGE 36864
#define DN_SMEM (1024 + 2 * DN_STAGE)   // 74752

__global__ void __launch_bounds__(512, 1)
dn_mma(const float* __restrict__ Wd, const float* __restrict__ wsd,
       float* __restrict__ out) {
    extern __shared__ char smem[];
    int tid = threadIdx.x;
    int wi = blockIdx.y;
    if (wi >= g_nwork) return;
    int code = g_work[wi];
    int z = code >> 16;
    int mt = code & 0xffff;
    bool SH = (z == E_EXP);
    int ne = SH ? T_TOK : g_cnt[z];
    int m0 = mt * 128;
    int n0 = blockIdx.x * 128;
    const float* wdp = SH ? wsd : (Wd + (size_t)z * D_DIM * F_DIM);
    const __half* hsrc = SH ? g_hsp : g_hp;

    int* s_pair = (int*)smem;
    if (tid < 128) {
        int m = m0 + tid;
        s_pair[tid] = SH ? m : ((m < ne) ? g_pairs[z * T_TOK + m] : g_pairs[z * T_TOK]);
    }
    __syncthreads();

    const __half* haptr[2];
    unsigned soA[2];
#pragma unroll
    for (int j = 0; j < 2; ++j) {
        int idx = tid + 512 * j;
        int row = idx >> 3, c8 = idx & 7;
        haptr[j] = hsrc + (size_t)s_pair[row] * F_DIM + c8 * 8;
        soA[j]   = row * APITCH + c8 * 16;
    }
    const int c4 = tid & 15;
    const int rbB = tid >> 4;
    const float* bptr[4];
#pragma unroll
    for (int j = 0; j < 4; ++j)
        bptr[j] = wdp + (size_t)(n0 + rbB + 32 * j) * F_DIM + c4 * 4;

    const int wid = tid >> 5, lane = tid & 31;
    const int wm = wid >> 2, wn = wid & 3;
    const int ksrot = wid & 3;

    float acc[2][4][4] = {};

    uint4  rha[2];
    float4 rwb[4];
#pragma unroll
    for (int j = 0; j < 2; ++j) rha[j] = *(const uint4*)(haptr[j]);
#pragma unroll
    for (int j = 0; j < 4; ++j) rwb[j] = *(const float4*)(bptr[j]);

    const uint32_t a_row = wm * 32 + (lane & 15);
    const uint32_t a_colb = (lane >> 4) * 16;
    const uint32_t b_row = wn * 32 + ((lane >> 3) >> 1) * 8 + (lane & 7);
    const uint32_t b_colb = ((lane >> 3) & 1) * 16;

#define DN_STORE(BUF) do { \
    char* b_ = (BUF); \
    _Pragma("unroll") \
    for (int j = 0; j < 2; ++j) \
        *(uint4*)(b_ + DN_A + soA[j]) = rha[j]; \
    _Pragma("unroll") \
    for (int j = 0; j < 4; ++j) { \
        char* p = b_ + (rbB + 32 * j) * APITCH + c4 * 8; \
        h16_store4(p + DN_B_HI, rwb[j]); \
    } \
} while (0)

    DN_STORE(smem + 1024);
    __syncthreads();

    for (int ch = 0; ch < 32; ++ch) {
        if (ch < 31) {
            int k0 = (ch + 1) * 64;
#pragma unroll
            for (int j = 0; j < 2; ++j) rha[j] = *(const uint4*)(haptr[j] + k0);
#pragma unroll
            for (int j = 0; j < 4; ++j) rwb[j] = *(const float4*)(bptr[j] + k0);
        }
        {
            char* cur = smem + 1024 + (ch & 1) * DN_STAGE;
            uint32_t abase = smem_u32(cur) + DN_A;
            uint32_t bbase = smem_u32(cur) + DN_B_HI;
#pragma unroll
            for (int i = 0; i < 4; ++i) {
                int ks = (i + ksrot) & 3;
                uint32_t koff = (uint32_t)ks * 32;
                uint32_t ah[2][4];
#pragma unroll
                for (int mt2 = 0; mt2 < 2; ++mt2) {
                    uint32_t ad = abase + (a_row + mt2 * 16) * APITCH + koff + a_colb;
                    ldm4(ah[mt2], ad);
                }
                uint32_t bh[8];
#pragma unroll
                for (int p2 = 0; p2 < 2; ++p2) {
                    uint32_t bd = bbase + (b_row + p2 * 16) * APITCH + koff + b_colb;
                    ldm4(&bh[p2 * 4], bd);
                }
#pragma unroll
                for (int mt2 = 0; mt2 < 2; ++mt2)
#pragma unroll
                    for (int nt = 0; nt < 4; ++nt)
                        mma16816(acc[mt2][nt], ah[mt2], &bh[nt * 2]);
            }
        }
        if (ch < 31) {
            char* nxt = smem + 1024 + ((ch + 1) & 1) * DN_STAGE;
            DN_STORE(nxt);
            __syncthreads();
        }
    }
    __syncthreads();

    float* stg = (float*)(smem + 1024);
#pragma unroll
    for (int mt2 = 0; mt2 < 2; ++mt2)
#pragma unroll
        for (int nt = 0; nt < 4; ++nt) {
            int r = wm * 32 + mt2 * 16 + (lane >> 2);
            int c = wn * 32 + nt * 8 + (lane & 3) * 2;
            *(float2*)&stg[r * 132 + c]       = make_float2(acc[mt2][nt][0], acc[mt2][nt][1]);
            *(float2*)&stg[(r + 8) * 132 + c] = make_float2(acc[mt2][nt][2], acc[mt2][nt][3]);
        }
    __syncthreads();

    {
        int r = tid >> 2;
        int c0 = (tid & 3) * 32;
        float* drow;
        if (SH) drow = out + (size_t)(m0 + r) * D_DIM + n0 + c0;
        else    drow = g_y + (size_t)s_pair[r] * D_DIM + n0 + c0;
#pragma unroll
        for (int jj = 0; jj < 32; jj += 4) {
            float4 v = make_float4(stg[r * 132 + c0 + jj], stg[r * 132 + c0 + jj + 1],
                                   stg[r * 132 + c0 + jj + 2], stg[r * 132 + c0 + jj + 3]);
            *(float4*)(drow + jj) = v;
        }
    }
}

// ================= combine: out += sum_k w_k * y_pair =================
__global__ void combine_kernel(float* __restrict__ out) {
    int t = blockIdx.x;
    int c = threadIdx.x * 4;
    float4 o = *(float4*)(out + (size_t)t * D_DIM + c);
#pragma unroll
    for (int k = 0; k < TOPK; ++k) {
        int pair = t * TOPK + k;
        float w = g_w[pair];
        float4 y = *(const float4*)(g_y + (size_t)pair * D_DIM + c);
        o.x += w * y.x; o.y += w * y.y; o.z += w * y.z; o.w += w * y.w;
    }
    *(float4*)(out + (size_t)t * D_DIM + c) = o;
}

// ---------------- launch ----------------
extern "C" void kernel_launch(void* const* d_in, const int* in_sizes, int n_in,
                              void* d_out, int out_size) {
    const float* x    = (const float*)d_in[0];
    const float* gw   = (const float*)d_in[1];
    const float* bias = (const float*)d_in[2];
    const float* wg   = (const float*)d_in[3];
    const float* wu   = (const float*)d_in[4];
    const float* wd   = (const float*)d_in[5];
    const float* wsg  = (const float*)d_in[6];
    const float* wsu  = (const float*)d_in[7];
    const float* wsd  = (const float*)d_in[8];
    float* out = (float*)d_out;

    static int attr_done = 0;
    if (!attr_done) {
        cudaFuncSetAttribute(gu_mma, cudaFuncAttributeMaxDynamicSharedMemorySize, GU_SMEM);
        cudaFuncSetAttribute(dn_mma, cudaFuncAttributeMaxDynamicSharedMemorySize, DN_SMEM);
        attr_done = 1;
    }

    zero_kernel<<<1, 32>>>();
    router_kernel<<<T_TOK, 128>>>(x, gw, bias);

    float* tail = (out_size >= T_TOK * D_DIM + E_EXP + 1) ? (out + T_TOK * D_DIM) : nullptr;
    stats_kernel<<<1, 32>>>(tail);

    // gate+up: compact work list (routed + shared)
    gu_mma<<<dim3(F_DIM / 64, MAXW), 512, GU_SMEM>>>(x, wg, wu, wsg, wsu);

    // down: compact work list (routed -> g_y, shared -> out)
    dn_mma<<<dim3(D_DIM / 128, MAXW), 512, DN_SMEM>>>(wd, wsd, out);

    // weighted combine
    combine_kernel<<<T_TOK, 256>>>(out);
}